// round 9
// baseline (speedup 1.0000x reference)
#include <cuda_runtime.h>
#include <math.h>
#include <stdint.h>

#define B_    8
#define CCH   256
#define NPIX  1024
#define HID   1024
#define NTOK  (B_ * NPIX)   // 8192

// scratch layout (floats)
static const size_t IC_SZ  = (size_t)B_ * NPIX * 6400;   // 52.4M
static const size_t C_SZ   = (size_t)NTOK * CCH;         // 2M
static const size_t QKV_SZ = (size_t)NTOK * 768;         // 6M
static const size_t H_SZ   = (size_t)NTOK * HID;         // 8M
__device__ float g_scratch[92ull * 1024 * 1024];

extern __shared__ char dyn_smem[];

__device__ __forceinline__ float to_tf32(float x) {
    float r;
    asm("cvt.rna.tf32.f32 %0, %1;" : "=f"(r) : "f"(x));
    return r;
}
__device__ __forceinline__ uint32_t smem_addr(const void* p) {
    return (uint32_t)__cvta_generic_to_shared(p);
}
__device__ __forceinline__ void cp16(uint32_t dst, const void* src) {
    asm volatile("cp.async.ca.shared.global [%0], [%1], 16;" :: "r"(dst), "l"(src));
}
// k-permutation within each 8-block: newpos(k) = (k&3)*2 + ((k>>2)&1)
__device__ __forceinline__ int permk(int k) {
    return (k & ~7) | (((k & 3) << 1) | ((k >> 2) & 1));
}

#define MMA_TF32(acc, a0, a1, a2, a3, b0, b1) \
    asm volatile( \
        "mma.sync.aligned.m16n8k8.row.col.f32.tf32.tf32.f32 " \
        "{%0,%1,%2,%3}, {%4,%5,%6,%7}, {%8,%9}, {%0,%1,%2,%3};" \
        : "+f"((acc)[0]), "+f"((acc)[1]), "+f"((acc)[2]), "+f"((acc)[3]) \
        : "r"(a0), "r"(a1), "r"(a2), "r"(a3), "r"(b0), "r"(b1))

// ---------------------------------------------------------------------------
// fused weight prep: tf32-round + k-permute, all 12 weights in one launch.
// ---------------------------------------------------------------------------
struct PrepArgs {
    const float* src[12];
    float*       dst[12];
    int          len[12];
};
__global__ __launch_bounds__(256)
void prep_all(PrepArgs a)
{
    int i = blockIdx.x * 256 + threadIdx.x;
#pragma unroll
    for (int s = 0; s < 12; s++) {
        if (i < a.len[s]) {
            a.dst[s][permk(i)] = to_tf32(__ldg(a.src[s] + i));
            return;
        }
        i -= a.len[s];
    }
}

// ---------------------------------------------------------------------------
// tf32 mma.sync GEMM on PRE-PERMUTED tf32 inputs (A and Wt both [rows][K] with
// k-permuted columns). Y (+residual R) in NORMAL fp32 layout.
// Block 128x128x32, 8 warps, cp.async double buffer, smem [2][128][40].
// ---------------------------------------------------------------------------
__global__ __launch_bounds__(256, 2)
void gemm_tc(const float* __restrict__ A, size_t ldA,
             const float* __restrict__ Wt,
             const float* __restrict__ R, size_t ldR,
             float* __restrict__ Y, size_t ldY,
             int K, int transY)
{
    float* As = (float*)dyn_smem;        // [2][128*40]
    float* Bs = As + 2 * 5120;           // [2][128*40]

    const int t = threadIdx.x;
    const int wid = t >> 5, lane = t & 31;
    const int g = lane >> 2, tig = lane & 3;
    const int warp_m = (wid & 1) * 64;
    const int warp_n = (wid >> 1) * 32;
    const int r0l = t >> 3, q0l = t & 7;

    const float* Ab = A  + (size_t)blockIdx.z * NPIX * ldA + (size_t)blockIdx.x * 128 * ldA;
    const float* Bb = Wt + (size_t)blockIdx.y * 128 * (size_t)K;

    const uint32_t sA = smem_addr(As), sB = smem_addr(Bs);

    float acc[4][4][4];
#pragma unroll
    for (int im = 0; im < 4; im++)
#pragma unroll
        for (int in = 0; in < 4; in++)
#pragma unroll
            for (int c = 0; c < 4; c++) acc[im][in][c] = 0.f;

    const int nk = K >> 5;

#pragma unroll
    for (int i = 0; i < 4; i++) {
        const int r = r0l + i * 32;
        cp16(sA + (uint32_t)(r * 40 + q0l * 4) * 4, Ab + (size_t)r * ldA + q0l * 4);
        cp16(sB + (uint32_t)(r * 40 + q0l * 4) * 4, Bb + (size_t)r * K   + q0l * 4);
    }
    asm volatile("cp.async.commit_group;");

    for (int c = 0; c < nk; c++) {
        asm volatile("cp.async.wait_group 0;");
        __syncthreads();
        if (c + 1 < nk) {
            const int kk = (c + 1) << 5;
            const uint32_t boff = (uint32_t)((c + 1) & 1) * 5120;
#pragma unroll
            for (int i = 0; i < 4; i++) {
                const int r = r0l + i * 32;
                cp16(sA + (boff + r * 40 + q0l * 4) * 4, Ab + (size_t)r * ldA + kk + q0l * 4);
                cp16(sB + (boff + r * 40 + q0l * 4) * 4, Bb + (size_t)r * K   + kk + q0l * 4);
            }
            asm volatile("cp.async.commit_group;");
        }
        const float* Ac = As + (c & 1) * 5120;
        const float* Bc = Bs + (c & 1) * 5120;
#pragma unroll
        for (int ks = 0; ks < 4; ks++) {
            const int k0 = ks * 8;
            float2 au[4], al[4];
#pragma unroll
            for (int im = 0; im < 4; im++) {
                au[im] = *(const float2*)&Ac[(warp_m + im * 16 + g) * 40 + k0 + 2 * tig];
                al[im] = *(const float2*)&Ac[(warp_m + im * 16 + g + 8) * 40 + k0 + 2 * tig];
            }
#pragma unroll
            for (int in = 0; in < 4; in++) {
                const float2 bv = *(const float2*)&Bc[(warp_n + in * 8 + g) * 40 + k0 + 2 * tig];
#pragma unroll
                for (int im = 0; im < 4; im++) {
                    MMA_TF32(acc[im][in],
                             __float_as_uint(au[im].x), __float_as_uint(al[im].x),
                             __float_as_uint(au[im].y), __float_as_uint(al[im].y),
                             __float_as_uint(bv.x), __float_as_uint(bv.y));
                }
            }
        }
    }

    const int b = blockIdx.z;
    if (!transY) {
        float* Yb = Y + (size_t)b * NPIX * ldY;
        const float* Rb = R ? R + (size_t)b * NPIX * ldR : (const float*)0;
#pragma unroll
        for (int im = 0; im < 4; im++) {
#pragma unroll
            for (int half = 0; half < 2; half++) {
                const int tok = blockIdx.x * 128 + warp_m + im * 16 + g + half * 8;
#pragma unroll
                for (int in = 0; in < 4; in++) {
                    const int col = blockIdx.y * 128 + warp_n + in * 8 + tig * 2;
                    float2 v;
                    v.x = acc[im][in][half * 2 + 0];
                    v.y = acc[im][in][half * 2 + 1];
                    if (Rb) {
                        float2 rr = *(const float2*)(Rb + (size_t)tok * ldR + col);
                        v.x += rr.x; v.y += rr.y;
                    }
                    *(float2*)(Yb + (size_t)tok * ldY + col) = v;
                }
            }
        }
    } else {
        float* Yb = Y + (size_t)b * ldY * NPIX;
        const float* Rb = R ? R + (size_t)b * NPIX * ldR : (const float*)0;
#pragma unroll
        for (int im = 0; im < 4; im++) {
#pragma unroll
            for (int half = 0; half < 2; half++) {
                const int tok = blockIdx.x * 128 + warp_m + im * 16 + g + half * 8;
#pragma unroll
                for (int in = 0; in < 4; in++) {
                    const int col = blockIdx.y * 128 + warp_n + in * 8 + tig * 2;
                    float v0 = acc[im][in][half * 2 + 0];
                    float v1 = acc[im][in][half * 2 + 1];
                    if (Rb) {
                        float2 rr = *(const float2*)(Rb + (size_t)tok * ldR + col);
                        v0 += rr.x; v1 += rr.y;
                    }
                    Yb[(size_t)(col + 0) * NPIX + tok] = v0;
                    Yb[(size_t)(col + 1) * NPIX + tok] = v1;
                }
            }
        }
    }
}

// ---------------------------------------------------------------------------
// im2col: NCHW -> [B][1024 tok][C*KS*KS], tf32-rounded, k-permuted.
// ---------------------------------------------------------------------------
template <int KS>
__global__ __launch_bounds__(256)
void im2col_kernel(const float* __restrict__ in, float* __restrict__ out)
{
    constexpr int PAD  = KS / 2;
    constexpr int TAPS = KS * KS;
    constexpr int KTOT = CCH * TAPS;
    __shared__ float smv[64 * KS * 36];
    const int c0 = blockIdx.x * 64;
    const int h  = blockIdx.y;
    const int b  = blockIdx.z;
    const int t  = threadIdx.x;

    for (int e = t; e < 64 * KS * 36; e += 256) {
        const int cc = e % 36;
        const int r  = (e / 36) % KS;
        const int c  = e / (36 * KS);
        const int hh = h + r - PAD;
        const int ww = cc - PAD;
        float v = 0.f;
        if (hh >= 0 && hh < 32 && ww >= 0 && ww < 32)
            v = in[((size_t)b * CCH + c0 + c) * NPIX + hh * 32 + ww];
        smv[(c * KS + r) * 36 + cc] = v;
    }
    __syncthreads();
    for (int e = t; e < 32 * 64 * TAPS; e += 256) {
        const int w   = e / (64 * TAPS);
        const int rem = e % (64 * TAPS);
        const int c   = rem / TAPS;
        const int tap = rem % TAPS;
        const int ky  = tap / KS, kx = tap % KS;
        const int k   = (c0 + c) * TAPS + tap;
        out[((size_t)b * NPIX + h * 32 + w) * KTOT + permk(k)] =
            to_tf32(smv[(c * KS + ky) * 36 + (w + kx)]);
    }
}

// ---------------------------------------------------------------------------
// LayerNorm over channels, token-major [8192][256]. Warp per token.
// Output: tf32-rounded, k-permuted (GEMM A operand).
// ---------------------------------------------------------------------------
__global__ __launch_bounds__(256)
void ln_kernel(const float* __restrict__ x, const float* __restrict__ w,
               const float* __restrict__ bs, float* __restrict__ y)
{
    const int warp = threadIdx.x >> 5, lane = threadIdx.x & 31;
    const size_t tok = (size_t)blockIdx.x * 8 + warp;
    const float* xr = x + tok * CCH;
    float4 v0 = *(const float4*)(xr + lane * 4);
    float4 v1 = *(const float4*)(xr + 128 + lane * 4);
    float s  = v0.x + v0.y + v0.z + v0.w + v1.x + v1.y + v1.z + v1.w;
    float s2 = v0.x*v0.x + v0.y*v0.y + v0.z*v0.z + v0.w*v0.w
             + v1.x*v1.x + v1.y*v1.y + v1.z*v1.z + v1.w*v1.w;
#pragma unroll
    for (int o = 16; o > 0; o >>= 1) {
        s  += __shfl_xor_sync(0xffffffffu, s,  o);
        s2 += __shfl_xor_sync(0xffffffffu, s2, o);
    }
    const float mu = s * (1.f / 256.f);
    const float is = rsqrtf(s2 * (1.f / 256.f) - mu * mu + 1e-5f);
    float4 w0 = *(const float4*)(w + lane * 4);
    float4 w1 = *(const float4*)(w + 128 + lane * 4);
    float4 b0 = *(const float4*)(bs + lane * 4);
    float4 b1 = *(const float4*)(bs + 128 + lane * 4);
    float* yr = y + tok * CCH;
    float r0[4], r1[4];
    r0[0] = (v0.x - mu) * is * w0.x + b0.x; r0[1] = (v0.y - mu) * is * w0.y + b0.y;
    r0[2] = (v0.z - mu) * is * w0.z + b0.z; r0[3] = (v0.w - mu) * is * w0.w + b0.w;
    r1[0] = (v1.x - mu) * is * w1.x + b1.x; r1[1] = (v1.y - mu) * is * w1.y + b1.y;
    r1[2] = (v1.z - mu) * is * w1.z + b1.z; r1[3] = (v1.w - mu) * is * w1.w + b1.w;
#pragma unroll
    for (int j = 0; j < 4; j++) {
        yr[permk(lane * 4 + j)]       = to_tf32(r0[j]);
        yr[permk(128 + lane * 4 + j)] = to_tf32(r1[j]);
    }
}

// ---------------------------------------------------------------------------
// Flash attention, tf32 mma, PERMUTED fragment layout (all frag loads LDS.64).
// qkv [B][1024][768] token-major; out [B][1024][256] tf32 k-permuted.
// Block 128 queries / 8 warps; K/V tiles 64, double buffered.
// Softmax 1/8 scale folded into Q staging (exact, power of 2).
// ---------------------------------------------------------------------------
__global__ __launch_bounds__(256, 1)
void attn_kernel(const float* __restrict__ qkv, float* __restrict__ out)
{
    float* sm = (float*)dyn_smem;
    float* Qs = sm;                      // [128][68]  d-permuted
    float* Ks = Qs + 128 * 68;           // [2][64][68] d-permuted
    float* Vt = Ks + 2 * 64 * 68;        // [2][64][68] (d, key) key-permuted cols
    float* Ps = Vt + 2 * 64 * 68;        // [128][68]  key-permuted

    const int b = blockIdx.z, h = blockIdx.y;
    const int q0 = blockIdx.x * 128;
    const int hq = h * 64;
    const float* base = qkv + (size_t)b * NPIX * 768;

    const int t = threadIdx.x;
    const int wid = t >> 5, lane = t & 31;
    const int g = lane >> 2, tig = lane & 3;
    const int w16 = wid * 16;

    // Q: scale by 1/8, tf32, d-permuted.  pos(c*4+j) = (c>>1)*8 + 2j + (c&1)
#pragma unroll
    for (int i = 0; i < 8; i++) {
        const int e = t + i * 256;
        const int r = e >> 4, c = e & 15;
        const int pbase = (c >> 1) * 8 + (c & 1);
        float4 v = *(const float4*)(base + (size_t)(q0 + r) * 768 + hq + c * 4);
        Qs[r * 68 + pbase + 0] = to_tf32(v.x * 0.125f);
        Qs[r * 68 + pbase + 2] = to_tf32(v.y * 0.125f);
        Qs[r * 68 + pbase + 4] = to_tf32(v.z * 0.125f);
        Qs[r * 68 + pbase + 6] = to_tf32(v.w * 0.125f);
    }

    float oc[8][4];
#pragma unroll
    for (int n = 0; n < 8; n++)
#pragma unroll
        for (int c = 0; c < 4; c++) oc[n][c] = 0.f;
    float m0r = -1e30f, m1r = -1e30f, l0r = 0.f, l1r = 0.f;

    const int rkv = t & 63;
    const int pkv = (rkv & ~7) | (((rkv & 3) << 1) | ((rkv >> 2) & 1)); // permuted key col
    float4 kvr[4], vvr[4];
#pragma unroll
    for (int i = 0; i < 4; i++) {
        const int e = t + i * 256;
        const int rk = e >> 4, ck = e & 15;
        kvr[i] = *(const float4*)(base + (size_t)rk * 768 + 256 + hq + ck * 4);
        const int cv = (t >> 6) + i * 4;
        vvr[i] = *(const float4*)(base + (size_t)rkv * 768 + 512 + hq + cv * 4);
    }
    {
        float* Kb = Ks;
        float* Vb = Vt;
#pragma unroll
        for (int i = 0; i < 4; i++) {
            const int e = t + i * 256;
            const int rk = e >> 4, ck = e & 15;
            const int pb = (ck >> 1) * 8 + (ck & 1);
            Kb[rk * 68 + pb + 0] = to_tf32(kvr[i].x);
            Kb[rk * 68 + pb + 2] = to_tf32(kvr[i].y);
            Kb[rk * 68 + pb + 4] = to_tf32(kvr[i].z);
            Kb[rk * 68 + pb + 6] = to_tf32(kvr[i].w);
            const int cv = (t >> 6) + i * 4;
            Vb[(cv * 4 + 0) * 68 + pkv] = to_tf32(vvr[i].x);
            Vb[(cv * 4 + 1) * 68 + pkv] = to_tf32(vvr[i].y);
            Vb[(cv * 4 + 2) * 68 + pkv] = to_tf32(vvr[i].z);
            Vb[(cv * 4 + 3) * 68 + pkv] = to_tf32(vvr[i].w);
        }
    }
    __syncthreads();

    const int P0 = ((tig & 1) << 2) | (tig >> 1);   // perm(2*tig); perm(2*tig+1)=P0+2

    for (int tile = 0; tile < 16; tile++) {
        const int buf = tile & 1;
        float* Kb = Ks + buf * 64 * 68;
        float* Vb = Vt + buf * 64 * 68;

        if (tile < 15) {
            const size_t m0 = (size_t)(tile + 1) * 64;
#pragma unroll
            for (int i = 0; i < 4; i++) {
                const int e = t + i * 256;
                const int rk = e >> 4, ck = e & 15;
                kvr[i] = *(const float4*)(base + (m0 + rk) * 768 + 256 + hq + ck * 4);
                const int cv = (t >> 6) + i * 4;
                vvr[i] = *(const float4*)(base + (m0 + rkv) * 768 + 512 + hq + cv * 4);
            }
        }

        // S = (Q/8) K^T   — all frag loads LDS.64
        float s[8][4];
#pragma unroll
        for (int n = 0; n < 8; n++)
#pragma unroll
            for (int c = 0; c < 4; c++) s[n][c] = 0.f;
#pragma unroll
        for (int ks = 0; ks < 8; ks++) {
            const int k0 = ks * 8;
            const float2 au = *(const float2*)&Qs[(w16 + g) * 68 + k0 + 2 * tig];
            const float2 al = *(const float2*)&Qs[(w16 + g + 8) * 68 + k0 + 2 * tig];
#pragma unroll
            for (int n = 0; n < 8; n++) {
                const float2 bv = *(const float2*)&Kb[(n * 8 + g) * 68 + k0 + 2 * tig];
                MMA_TF32(s[n],
                         __float_as_uint(au.x), __float_as_uint(al.x),
                         __float_as_uint(au.y), __float_as_uint(al.y),
                         __float_as_uint(bv.x), __float_as_uint(bv.y));
            }
        }

        // online softmax (rows g and g+8, quad-reduced)
        float t0 = -1e30f, t1 = -1e30f;
#pragma unroll
        for (int n = 0; n < 8; n++) {
            t0 = fmaxf(t0, fmaxf(s[n][0], s[n][1]));
            t1 = fmaxf(t1, fmaxf(s[n][2], s[n][3]));
        }
        t0 = fmaxf(t0, __shfl_xor_sync(0xffffffffu, t0, 1));
        t0 = fmaxf(t0, __shfl_xor_sync(0xffffffffu, t0, 2));
        t1 = fmaxf(t1, __shfl_xor_sync(0xffffffffu, t1, 1));
        t1 = fmaxf(t1, __shfl_xor_sync(0xffffffffu, t1, 2));
        const float nm0 = fmaxf(m0r, t0), nm1 = fmaxf(m1r, t1);
        const float cr0 = __expf(m0r - nm0), cr1 = __expf(m1r - nm1);
        m0r = nm0; m1r = nm1;
        float ls0 = 0.f, ls1 = 0.f;
#pragma unroll
        for (int n = 0; n < 8; n++) {
            const float p0 = __expf(s[n][0] - nm0);
            const float p1 = __expf(s[n][1] - nm0);
            const float p2 = __expf(s[n][2] - nm1);
            const float p3 = __expf(s[n][3] - nm1);
            ls0 += p0 + p1; ls1 += p2 + p3;
            float* r0p = &Ps[(w16 + g) * 68 + n * 8];
            float* r1p = &Ps[(w16 + g + 8) * 68 + n * 8];
            r0p[P0]     = to_tf32(p0);
            r0p[P0 + 2] = to_tf32(p1);
            r1p[P0]     = to_tf32(p2);
            r1p[P0 + 2] = to_tf32(p3);
        }
        ls0 += __shfl_xor_sync(0xffffffffu, ls0, 1);
        ls0 += __shfl_xor_sync(0xffffffffu, ls0, 2);
        ls1 += __shfl_xor_sync(0xffffffffu, ls1, 1);
        ls1 += __shfl_xor_sync(0xffffffffu, ls1, 2);
        l0r = l0r * cr0 + ls0;
        l1r = l1r * cr1 + ls1;
#pragma unroll
        for (int n = 0; n < 8; n++) {
            oc[n][0] *= cr0; oc[n][1] *= cr0;
            oc[n][2] *= cr1; oc[n][3] *= cr1;
        }
        __syncwarp();

        // O += P V — all frag loads LDS.64
#pragma unroll
        for (int ks = 0; ks < 8; ks++) {
            const int k0 = ks * 8;
            const float2 au = *(const float2*)&Ps[(w16 + g) * 68 + k0 + 2 * tig];
            const float2 al = *(const float2*)&Ps[(w16 + g + 8) * 68 + k0 + 2 * tig];
#pragma unroll
            for (int n = 0; n < 8; n++) {
                const float2 bv = *(const float2*)&Vb[(n * 8 + g) * 68 + k0 + 2 * tig];
                MMA_TF32(oc[n],
                         __float_as_uint(au.x), __float_as_uint(al.x),
                         __float_as_uint(au.y), __float_as_uint(al.y),
                         __float_as_uint(bv.x), __float_as_uint(bv.y));
            }
        }

        if (tile < 15) {
            __syncthreads();
            float* Kn = Ks + (buf ^ 1) * 64 * 68;
            float* Vn = Vt + (buf ^ 1) * 64 * 68;
#pragma unroll
            for (int i = 0; i < 4; i++) {
                const int e = t + i * 256;
                const int rk = e >> 4, ck = e & 15;
                const int pb = (ck >> 1) * 8 + (ck & 1);
                Kn[rk * 68 + pb + 0] = to_tf32(kvr[i].x);
                Kn[rk * 68 + pb + 2] = to_tf32(kvr[i].y);
                Kn[rk * 68 + pb + 4] = to_tf32(kvr[i].z);
                Kn[rk * 68 + pb + 6] = to_tf32(kvr[i].w);
                const int cv = (t >> 6) + i * 4;
                Vn[(cv * 4 + 0) * 68 + pkv] = to_tf32(vvr[i].x);
                Vn[(cv * 4 + 1) * 68 + pkv] = to_tf32(vvr[i].y);
                Vn[(cv * 4 + 2) * 68 + pkv] = to_tf32(vvr[i].z);
                Vn[(cv * 4 + 3) * 68 + pkv] = to_tf32(vvr[i].w);
            }
            __syncthreads();
        }
    }

    // epilogue: att output tf32 + d-permuted (feeds GEMM A).
    const float i0 = 1.f / l0r, i1 = 1.f / l1r;
    float* ob = out + (size_t)b * NPIX * CCH;
#pragma unroll
    for (int n = 0; n < 8; n++) {
        float* r0p = ob + (size_t)(q0 + w16 + g) * CCH + hq + n * 8;
        float* r1p = ob + (size_t)(q0 + w16 + g + 8) * CCH + hq + n * 8;
        r0p[P0]     = to_tf32(oc[n][0] * i0);
        r0p[P0 + 2] = to_tf32(oc[n][1] * i0);
        r1p[P0]     = to_tf32(oc[n][2] * i1);
        r1p[P0 + 2] = to_tf32(oc[n][3] * i1);
    }
}

// ---------------------------------------------------------------------------
// Depthwise 3x3 + exact GELU, token-major [8192][1024].
// Output tf32 + permuted (h2 feeds GEMM A).
// ---------------------------------------------------------------------------
__global__ __launch_bounds__(256)
void dwgelu_kernel(const float* __restrict__ x, const float* __restrict__ wd,
                   float* __restrict__ y)
{
    __shared__ float tile[10][34][32];
    const int c0 = blockIdx.x * 32;
    const int r0 = blockIdx.y * 8;
    const int b  = blockIdx.z;
    const int t  = threadIdx.x;
    const int ch = t & 31;

    for (int e = t; e < 10 * 34 * 32; e += 256) {
        const int cc  = e & 31;
        const int col = (e >> 5) % 34;
        const int r   = e / (34 * 32);
        const int hh = r0 + r - 1, ww = col - 1;
        float v = 0.f;
        if (hh >= 0 && hh < 32 && ww >= 0 && ww < 32)
            v = x[((size_t)b * NPIX + hh * 32 + ww) * HID + c0 + cc];
        tile[r][col][cc] = v;
    }
    float w9[9];
#pragma unroll
    for (int i = 0; i < 9; i++) w9[i] = wd[(size_t)(c0 + ch) * 9 + i];
    const int pc = permk(c0 + ch);
    __syncthreads();

    for (int e = t; e < 8 * 32 * 32; e += 256) {
        const int w = (e >> 5) & 31;
        const int r = e >> 10;
        float a = 0.f;
#pragma unroll
        for (int ky = 0; ky < 3; ky++)
#pragma unroll
            for (int kx = 0; kx < 3; kx++)
                a += w9[ky * 3 + kx] * tile[r + ky][w + kx][ch];
        y[((size_t)b * NPIX + (r0 + r) * 32 + w) * HID + pc] =
            to_tf32(0.5f * a * (1.f + erff(a * 0.70710678118654752f)));
    }
}

// ---------------------------------------------------------------------------
extern "C" void kernel_launch(void* const* d_in, const int* in_sizes, int n_in,
                              void* d_out, int out_size)
{
    const float* aop      = (const float*)d_in[0];
    const float* dop      = (const float*)d_in[1];
    const float* w_qconv  = (const float*)d_in[2];
    const float* w_kvconv = (const float*)d_in[3];
    const float* lnq1_w   = (const float*)d_in[4];
    const float* lnq1_b   = (const float*)d_in[5];
    const float* lnkv1_w  = (const float*)d_in[6];
    const float* lnkv1_b  = (const float*)d_in[7];
    const float* lnq2_w   = (const float*)d_in[8];
    const float* lnq2_b   = (const float*)d_in[9];
    const float* lnkv2_w  = (const float*)d_in[10];
    const float* lnkv2_b  = (const float*)d_in[11];
    const float* lnffn_w  = (const float*)d_in[12];
    const float* lnffn_b  = (const float*)d_in[13];
    const float* saq_qkv  = (const float*)d_in[14];
    const float* saq_proj = (const float*)d_in[15];
    const float* sakv_qkv = (const float*)d_in[16];
    const float* sakv_proj= (const float*)d_in[17];
    const float* ca_q     = (const float*)d_in[18];
    const float* ca_k     = (const float*)d_in[19];
    const float* ca_v     = (const float*)d_in[20];
    const float* ca_proj  = (const float*)d_in[21];
    const float* leff_in  = (const float*)d_in[22];
    const float* leff_dw  = (const float*)d_in[23];
    const float* leff_out = (const float*)d_in[24];
    float* out = (float*)d_out;

    float* S = nullptr;
    cudaGetSymbolAddress((void**)&S, g_scratch);
    float* ic   = S;
    float* qb   = ic   + IC_SZ;
    float* kvb  = qb   + C_SZ;
    float* lnb  = kvb  + C_SZ;
    float* qn   = lnb  + C_SZ;
    float* kvn  = qn   + C_SZ;
    float* att  = kvn  + C_SZ;
    float* xbuf = att  + C_SZ;
    float* qkv  = xbuf + C_SZ;
    float* h1   = qkv  + QKV_SZ;
    float* h2   = h1   + H_SZ;
    float* wp   = h2   + H_SZ;

    // permuted tf32 weight copies
    float* p_wq3   = wp;
    float* p_wk5   = p_wq3   + 589824;
    float* p_saqkv = p_wk5   + 1638400;
    float* p_saprj = p_saqkv + 196608;
    float* p_skqkv = p_saprj + 65536;
    float* p_skprj = p_skqkv + 196608;
    float* p_caq   = p_skprj + 65536;
    float* p_cak   = p_caq   + 65536;
    float* p_cav   = p_cak   + 65536;
    float* p_caprj = p_cav   + 65536;
    float* p_lin   = p_caprj + 65536;
    float* p_lout  = p_lin   + 262144;

    const int GEMM_SM = 2 * 5120 * 2 * 4;    // 81920
    const int ATTN_SM = (128 * 68 + 2 * 64 * 68 + 2 * 64 * 68 + 128 * 68) * 4; // 139264
    cudaFuncSetAttribute(gemm_tc,     cudaFuncAttributeMaxDynamicSharedMemorySize, GEMM_SM);
    cudaFuncSetAttribute(attn_kernel, cudaFuncAttributeMaxDynamicSharedMemorySize, ATTN_SM);

    // fused weight prep (one launch)
    PrepArgs pa;
    pa.src[0] = w_qconv;   pa.dst[0] = p_wq3;   pa.len[0] = 589824;
    pa.src[1] = w_kvconv;  pa.dst[1] = p_wk5;   pa.len[1] = 1638400;
    pa.src[2] = saq_qkv;   pa.dst[2] = p_saqkv; pa.len[2] = 196608;
    pa.src[3] = saq_proj;  pa.dst[3] = p_saprj; pa.len[3] = 65536;
    pa.src[4] = sakv_qkv;  pa.dst[4] = p_skqkv; pa.len[4] = 196608;
    pa.src[5] = sakv_proj; pa.dst[5] = p_skprj; pa.len[5] = 65536;
    pa.src[6] = ca_q;      pa.dst[6] = p_caq;   pa.len[6] = 65536;
    pa.src[7] = ca_k;      pa.dst[7] = p_cak;   pa.len[7] = 65536;
    pa.src[8] = ca_v;      pa.dst[8] = p_cav;   pa.len[8] = 65536;
    pa.src[9] = ca_proj;   pa.dst[9] = p_caprj; pa.len[9] = 65536;
    pa.src[10] = leff_in;  pa.dst[10] = p_lin;  pa.len[10] = 262144;
    pa.src[11] = leff_out; pa.dst[11] = p_lout; pa.len[11] = 262144;
    int prep_total = 589824 + 1638400 + 2 * 196608 + 6 * 65536 + 2 * 262144;
    prep_all<<<(prep_total + 255) / 256, 256>>>(pa);

    const dim3 g256(8, 2, B_), g768(8, 6, B_), g1024t(8, 8, B_);
    const dim3 gattn(8, 4, B_);
    const dim3 gi2c(4, 32, B_);
    const dim3 gdw(32, 4, B_);

    // ---- q branch ----
    im2col_kernel<3><<<gi2c, 256>>>(aop, ic);
    gemm_tc<<<g256, 256, GEMM_SM>>>(ic, 2304, p_wq3, nullptr, 0, qb, 256, 2304, 0);
    ln_kernel<<<1024, 256>>>(qb, lnq1_w, lnq1_b, lnb);
    gemm_tc<<<g768, 256, GEMM_SM>>>(lnb, 256, p_saqkv, nullptr, 0, qkv, 768, 256, 0);
    attn_kernel<<<gattn, 256, ATTN_SM>>>(qkv, att);
    gemm_tc<<<g256, 256, GEMM_SM>>>(att, 256, p_saprj, qb, 256, qb, 256, 256, 0);
    ln_kernel<<<1024, 256>>>(qb, lnq2_w, lnq2_b, qn);

    // ---- kv branch ----
    im2col_kernel<5><<<gi2c, 256>>>(dop, ic);
    gemm_tc<<<g256, 256, GEMM_SM>>>(ic, 6400, p_wk5, nullptr, 0, kvb, 256, 6400, 0);
    ln_kernel<<<1024, 256>>>(kvb, lnkv1_w, lnkv1_b, lnb);
    gemm_tc<<<g768, 256, GEMM_SM>>>(lnb, 256, p_skqkv, nullptr, 0, qkv, 768, 256, 0);
    attn_kernel<<<gattn, 256, ATTN_SM>>>(qkv, att);
    gemm_tc<<<g256, 256, GEMM_SM>>>(att, 256, p_skprj, kvb, 256, kvb, 256, 256, 0);
    ln_kernel<<<1024, 256>>>(kvb, lnkv2_w, lnkv2_b, kvn);

    // ---- cross attention ----
    gemm_tc<<<g256, 256, GEMM_SM>>>(qn,  256, p_caq,   nullptr, 0, qkv,       768, 256, 0);
    gemm_tc<<<g256, 256, GEMM_SM>>>(kvn, 256, p_cak,   nullptr, 0, qkv + 256, 768, 256, 0);
    gemm_tc<<<g256, 256, GEMM_SM>>>(kvn, 256, p_cav,   nullptr, 0, qkv + 512, 768, 256, 0);
    attn_kernel<<<gattn, 256, ATTN_SM>>>(qkv, att);
    gemm_tc<<<g256, 256, GEMM_SM>>>(att, 256, p_caprj, qb, 256, xbuf, 256, 256, 0);

    // ---- LeFF ----
    ln_kernel<<<1024, 256>>>(xbuf, lnffn_w, lnffn_b, lnb);
    gemm_tc<<<g1024t, 256, GEMM_SM>>>(lnb, 256, p_lin, nullptr, 0, h1, 1024, 256, 0);
    dwgelu_kernel<<<gdw, 256>>>(h1, leff_dw, h2);
    gemm_tc<<<g256, 256, GEMM_SM>>>(h2, 1024, p_lout, xbuf, 256, out, 256, 1024, 1);
}

// round 10
// speedup vs baseline: 1.1089x; 1.1089x over previous
#include <cuda_runtime.h>
#include <math.h>
#include <stdint.h>

#define B_    8
#define CCH   256
#define NPIX  1024
#define HID   1024
#define NTOK  (B_ * NPIX)   // 8192

// scratch layout (floats)
static const size_t IC_SZ  = (size_t)B_ * NPIX * 6400;   // 52.4M
static const size_t C_SZ   = (size_t)NTOK * CCH;         // 2M
static const size_t QKV_SZ = (size_t)NTOK * 768;         // 6M
static const size_t H_SZ   = (size_t)NTOK * HID;         // 8M
__device__ float g_scratch[92ull * 1024 * 1024];

extern __shared__ char dyn_smem[];

__device__ __forceinline__ float to_tf32(float x) {
    float r;
    asm("cvt.rna.tf32.f32 %0, %1;" : "=f"(r) : "f"(x));
    return r;
}
__device__ __forceinline__ uint32_t smem_addr(const void* p) {
    return (uint32_t)__cvta_generic_to_shared(p);
}
__device__ __forceinline__ void cp16(uint32_t dst, const void* src) {
    asm volatile("cp.async.ca.shared.global [%0], [%1], 16;" :: "r"(dst), "l"(src));
}
// k-permutation within each 8-block: newpos(k) = (k&3)*2 + ((k>>2)&1)
__device__ __forceinline__ int permk(int k) {
    return (k & ~7) | (((k & 3) << 1) | ((k >> 2) & 1));
}

#define MMA_TF32(acc, a0, a1, a2, a3, b0, b1) \
    asm volatile( \
        "mma.sync.aligned.m16n8k8.row.col.f32.tf32.tf32.f32 " \
        "{%0,%1,%2,%3}, {%4,%5,%6,%7}, {%8,%9}, {%0,%1,%2,%3};" \
        : "+f"((acc)[0]), "+f"((acc)[1]), "+f"((acc)[2]), "+f"((acc)[3]) \
        : "r"(a0), "r"(a1), "r"(a2), "r"(a3), "r"(b0), "r"(b1))

// ---------------------------------------------------------------------------
// fused weight prep: tf32-round + k-permute, all 12 weights in one launch.
// ---------------------------------------------------------------------------
struct PrepArgs {
    const float* src[12];
    float*       dst[12];
    int          len[12];
};
__global__ __launch_bounds__(256)
void prep_all(PrepArgs a)
{
    int i = blockIdx.x * 256 + threadIdx.x;
#pragma unroll
    for (int s = 0; s < 12; s++) {
        if (i < a.len[s]) {
            a.dst[s][permk(i)] = to_tf32(__ldg(a.src[s] + i));
            return;
        }
        i -= a.len[s];
    }
}

// ---------------------------------------------------------------------------
// tf32 mma.sync GEMM on PRE-PERMUTED tf32 inputs (A and Wt both [rows][K] with
// k-permuted columns). Y (+residual R) in NORMAL fp32 layout.
// Block 128x128x32, 8 warps, cp.async double buffer, smem [2][128][40].
// ---------------------------------------------------------------------------
__global__ __launch_bounds__(256, 2)
void gemm_tc(const float* __restrict__ A, size_t ldA,
             const float* __restrict__ Wt,
             const float* __restrict__ R, size_t ldR,
             float* __restrict__ Y, size_t ldY,
             int K, int transY)
{
    float* As = (float*)dyn_smem;        // [2][128*40]
    float* Bs = As + 2 * 5120;           // [2][128*40]

    const int t = threadIdx.x;
    const int wid = t >> 5, lane = t & 31;
    const int g = lane >> 2, tig = lane & 3;
    const int warp_m = (wid & 1) * 64;
    const int warp_n = (wid >> 1) * 32;
    const int r0l = t >> 3, q0l = t & 7;

    const float* Ab = A  + (size_t)blockIdx.z * NPIX * ldA + (size_t)blockIdx.x * 128 * ldA;
    const float* Bb = Wt + (size_t)blockIdx.y * 128 * (size_t)K;

    const uint32_t sA = smem_addr(As), sB = smem_addr(Bs);

    float acc[4][4][4];
#pragma unroll
    for (int im = 0; im < 4; im++)
#pragma unroll
        for (int in = 0; in < 4; in++)
#pragma unroll
            for (int c = 0; c < 4; c++) acc[im][in][c] = 0.f;

    const int nk = K >> 5;

#pragma unroll
    for (int i = 0; i < 4; i++) {
        const int r = r0l + i * 32;
        cp16(sA + (uint32_t)(r * 40 + q0l * 4) * 4, Ab + (size_t)r * ldA + q0l * 4);
        cp16(sB + (uint32_t)(r * 40 + q0l * 4) * 4, Bb + (size_t)r * K   + q0l * 4);
    }
    asm volatile("cp.async.commit_group;");

    for (int c = 0; c < nk; c++) {
        asm volatile("cp.async.wait_group 0;");
        __syncthreads();
        if (c + 1 < nk) {
            const int kk = (c + 1) << 5;
            const uint32_t boff = (uint32_t)((c + 1) & 1) * 5120;
#pragma unroll
            for (int i = 0; i < 4; i++) {
                const int r = r0l + i * 32;
                cp16(sA + (boff + r * 40 + q0l * 4) * 4, Ab + (size_t)r * ldA + kk + q0l * 4);
                cp16(sB + (boff + r * 40 + q0l * 4) * 4, Bb + (size_t)r * K   + kk + q0l * 4);
            }
            asm volatile("cp.async.commit_group;");
        }
        const float* Ac = As + (c & 1) * 5120;
        const float* Bc = Bs + (c & 1) * 5120;
#pragma unroll
        for (int ks = 0; ks < 4; ks++) {
            const int k0 = ks * 8;
            float2 au[4], al[4];
#pragma unroll
            for (int im = 0; im < 4; im++) {
                au[im] = *(const float2*)&Ac[(warp_m + im * 16 + g) * 40 + k0 + 2 * tig];
                al[im] = *(const float2*)&Ac[(warp_m + im * 16 + g + 8) * 40 + k0 + 2 * tig];
            }
#pragma unroll
            for (int in = 0; in < 4; in++) {
                const float2 bv = *(const float2*)&Bc[(warp_n + in * 8 + g) * 40 + k0 + 2 * tig];
#pragma unroll
                for (int im = 0; im < 4; im++) {
                    MMA_TF32(acc[im][in],
                             __float_as_uint(au[im].x), __float_as_uint(al[im].x),
                             __float_as_uint(au[im].y), __float_as_uint(al[im].y),
                             __float_as_uint(bv.x), __float_as_uint(bv.y));
                }
            }
        }
    }

    const int b = blockIdx.z;
    if (!transY) {
        float* Yb = Y + (size_t)b * NPIX * ldY;
        const float* Rb = R ? R + (size_t)b * NPIX * ldR : (const float*)0;
#pragma unroll
        for (int im = 0; im < 4; im++) {
#pragma unroll
            for (int half = 0; half < 2; half++) {
                const int tok = blockIdx.x * 128 + warp_m + im * 16 + g + half * 8;
#pragma unroll
                for (int in = 0; in < 4; in++) {
                    const int col = blockIdx.y * 128 + warp_n + in * 8 + tig * 2;
                    float2 v;
                    v.x = acc[im][in][half * 2 + 0];
                    v.y = acc[im][in][half * 2 + 1];
                    if (Rb) {
                        float2 rr = *(const float2*)(Rb + (size_t)tok * ldR + col);
                        v.x += rr.x; v.y += rr.y;
                    }
                    *(float2*)(Yb + (size_t)tok * ldY + col) = v;
                }
            }
        }
    } else {
        float* Yb = Y + (size_t)b * ldY * NPIX;
        const float* Rb = R ? R + (size_t)b * NPIX * ldR : (const float*)0;
#pragma unroll
        for (int im = 0; im < 4; im++) {
#pragma unroll
            for (int half = 0; half < 2; half++) {
                const int tok = blockIdx.x * 128 + warp_m + im * 16 + g + half * 8;
#pragma unroll
                for (int in = 0; in < 4; in++) {
                    const int col = blockIdx.y * 128 + warp_n + in * 8 + tig * 2;
                    float v0 = acc[im][in][half * 2 + 0];
                    float v1 = acc[im][in][half * 2 + 1];
                    if (Rb) {
                        float2 rr = *(const float2*)(Rb + (size_t)tok * ldR + col);
                        v0 += rr.x; v1 += rr.y;
                    }
                    Yb[(size_t)(col + 0) * NPIX + tok] = v0;
                    Yb[(size_t)(col + 1) * NPIX + tok] = v1;
                }
            }
        }
    }
}

// ---------------------------------------------------------------------------
// im2col: NCHW -> [B][1024 tok][C*KS*KS], tf32-rounded, k-permuted.
// ---------------------------------------------------------------------------
template <int KS>
__global__ __launch_bounds__(256)
void im2col_kernel(const float* __restrict__ in, float* __restrict__ out)
{
    constexpr int PAD  = KS / 2;
    constexpr int TAPS = KS * KS;
    constexpr int KTOT = CCH * TAPS;
    __shared__ float smv[64 * KS * 36];
    const int c0 = blockIdx.x * 64;
    const int h  = blockIdx.y;
    const int b  = blockIdx.z;
    const int t  = threadIdx.x;

    for (int e = t; e < 64 * KS * 36; e += 256) {
        const int cc = e % 36;
        const int r  = (e / 36) % KS;
        const int c  = e / (36 * KS);
        const int hh = h + r - PAD;
        const int ww = cc - PAD;
        float v = 0.f;
        if (hh >= 0 && hh < 32 && ww >= 0 && ww < 32)
            v = in[((size_t)b * CCH + c0 + c) * NPIX + hh * 32 + ww];
        smv[(c * KS + r) * 36 + cc] = v;
    }
    __syncthreads();
    for (int e = t; e < 32 * 64 * TAPS; e += 256) {
        const int w   = e / (64 * TAPS);
        const int rem = e % (64 * TAPS);
        const int c   = rem / TAPS;
        const int tap = rem % TAPS;
        const int ky  = tap / KS, kx = tap % KS;
        const int k   = (c0 + c) * TAPS + tap;
        out[((size_t)b * NPIX + h * 32 + w) * KTOT + permk(k)] =
            to_tf32(smv[(c * KS + ky) * 36 + (w + kx)]);
    }
}

// ---------------------------------------------------------------------------
// LayerNorm over channels, token-major [8192][256]. Warp per token.
// Output: tf32-rounded, k-permuted (GEMM A operand).
// ---------------------------------------------------------------------------
__global__ __launch_bounds__(256)
void ln_kernel(const float* __restrict__ x, const float* __restrict__ w,
               const float* __restrict__ bs, float* __restrict__ y)
{
    const int warp = threadIdx.x >> 5, lane = threadIdx.x & 31;
    const size_t tok = (size_t)blockIdx.x * 8 + warp;
    const float* xr = x + tok * CCH;
    float4 v0 = *(const float4*)(xr + lane * 4);
    float4 v1 = *(const float4*)(xr + 128 + lane * 4);
    float s  = v0.x + v0.y + v0.z + v0.w + v1.x + v1.y + v1.z + v1.w;
    float s2 = v0.x*v0.x + v0.y*v0.y + v0.z*v0.z + v0.w*v0.w
             + v1.x*v1.x + v1.y*v1.y + v1.z*v1.z + v1.w*v1.w;
#pragma unroll
    for (int o = 16; o > 0; o >>= 1) {
        s  += __shfl_xor_sync(0xffffffffu, s,  o);
        s2 += __shfl_xor_sync(0xffffffffu, s2, o);
    }
    const float mu = s * (1.f / 256.f);
    const float is = rsqrtf(s2 * (1.f / 256.f) - mu * mu + 1e-5f);
    float4 w0 = *(const float4*)(w + lane * 4);
    float4 w1 = *(const float4*)(w + 128 + lane * 4);
    float4 b0 = *(const float4*)(bs + lane * 4);
    float4 b1 = *(const float4*)(bs + 128 + lane * 4);
    float* yr = y + tok * CCH;
    float r0[4], r1[4];
    r0[0] = (v0.x - mu) * is * w0.x + b0.x; r0[1] = (v0.y - mu) * is * w0.y + b0.y;
    r0[2] = (v0.z - mu) * is * w0.z + b0.z; r0[3] = (v0.w - mu) * is * w0.w + b0.w;
    r1[0] = (v1.x - mu) * is * w1.x + b1.x; r1[1] = (v1.y - mu) * is * w1.y + b1.y;
    r1[2] = (v1.z - mu) * is * w1.z + b1.z; r1[3] = (v1.w - mu) * is * w1.w + b1.w;
#pragma unroll
    for (int j = 0; j < 4; j++) {
        yr[permk(lane * 4 + j)]       = to_tf32(r0[j]);
        yr[permk(128 + lane * 4 + j)] = to_tf32(r1[j]);
    }
}

// ---------------------------------------------------------------------------
// Flash attention, tf32 mma (R8 layout: vectorizable staging, scalar frags).
// qkv [B][1024][768] token-major; out [B][1024][256] tf32 k-permuted.
// Block 128 queries / 8 warps; K/V tiles 64, double buffered.
// Softmax 1/8 scale folded into Q staging (exact, power of 2).
// ---------------------------------------------------------------------------
__global__ __launch_bounds__(256, 1)
void attn_kernel(const float* __restrict__ qkv, float* __restrict__ out)
{
    float* sm = (float*)dyn_smem;
    float* Qs = sm;                      // [128][68]
    float* Ks = Qs + 128 * 68;           // [2][64][68]
    float* Vt = Ks + 2 * 64 * 68;        // [2][64][68]  (d, key)
    float* Ps = Vt + 2 * 64 * 68;        // [128][68]

    const int b = blockIdx.z, h = blockIdx.y;
    const int q0 = blockIdx.x * 128;
    const int hq = h * 64;
    const float* base = qkv + (size_t)b * NPIX * 768;

    const int t = threadIdx.x;
    const int wid = t >> 5, lane = t & 31;
    const int g = lane >> 2, tig = lane & 3;
    const int w16 = wid * 16;

#pragma unroll
    for (int i = 0; i < 8; i++) {
        const int e = t + i * 256;
        const int r = e >> 4, c = e & 15;
        float4 v = *(const float4*)(base + (size_t)(q0 + r) * 768 + hq + c * 4);
        Qs[r * 68 + c * 4 + 0] = to_tf32(v.x * 0.125f);
        Qs[r * 68 + c * 4 + 1] = to_tf32(v.y * 0.125f);
        Qs[r * 68 + c * 4 + 2] = to_tf32(v.z * 0.125f);
        Qs[r * 68 + c * 4 + 3] = to_tf32(v.w * 0.125f);
    }

    float oc[8][4];
#pragma unroll
    for (int n = 0; n < 8; n++)
#pragma unroll
        for (int c = 0; c < 4; c++) oc[n][c] = 0.f;
    float m0r = -1e30f, m1r = -1e30f, l0r = 0.f, l1r = 0.f;

    const int rkv = t & 63;
    float4 kvr[4], vvr[4];
#pragma unroll
    for (int i = 0; i < 4; i++) {
        const int e = t + i * 256;
        const int rk = e >> 4, ck = e & 15;
        kvr[i] = *(const float4*)(base + (size_t)rk * 768 + 256 + hq + ck * 4);
        const int cv = (t >> 6) + i * 4;
        vvr[i] = *(const float4*)(base + (size_t)rkv * 768 + 512 + hq + cv * 4);
    }
    {
        float* Kb = Ks;
        float* Vb = Vt;
#pragma unroll
        for (int i = 0; i < 4; i++) {
            const int e = t + i * 256;
            const int rk = e >> 4, ck = e & 15;
            Kb[rk * 68 + ck * 4 + 0] = to_tf32(kvr[i].x);
            Kb[rk * 68 + ck * 4 + 1] = to_tf32(kvr[i].y);
            Kb[rk * 68 + ck * 4 + 2] = to_tf32(kvr[i].z);
            Kb[rk * 68 + ck * 4 + 3] = to_tf32(kvr[i].w);
            const int cv = (t >> 6) + i * 4;
            Vb[(cv * 4 + 0) * 68 + rkv] = to_tf32(vvr[i].x);
            Vb[(cv * 4 + 1) * 68 + rkv] = to_tf32(vvr[i].y);
            Vb[(cv * 4 + 2) * 68 + rkv] = to_tf32(vvr[i].z);
            Vb[(cv * 4 + 3) * 68 + rkv] = to_tf32(vvr[i].w);
        }
    }
    __syncthreads();

    const int P0 = ((tig & 1) << 2) | (tig >> 1);   // perm(2*tig); perm(2*tig+1)=P0+2

    for (int tile = 0; tile < 16; tile++) {
        const int buf = tile & 1;
        float* Kb = Ks + buf * 64 * 68;
        float* Vb = Vt + buf * 64 * 68;

        if (tile < 15) {
            const size_t m0 = (size_t)(tile + 1) * 64;
#pragma unroll
            for (int i = 0; i < 4; i++) {
                const int e = t + i * 256;
                const int rk = e >> 4, ck = e & 15;
                kvr[i] = *(const float4*)(base + (m0 + rk) * 768 + 256 + hq + ck * 4);
                const int cv = (t >> 6) + i * 4;
                vvr[i] = *(const float4*)(base + (m0 + rkv) * 768 + 512 + hq + cv * 4);
            }
        }

        // S = (Q/8) K^T
        float s[8][4];
#pragma unroll
        for (int n = 0; n < 8; n++)
#pragma unroll
            for (int c = 0; c < 4; c++) s[n][c] = 0.f;
#pragma unroll
        for (int ks = 0; ks < 8; ks++) {
            const int k0 = ks * 8;
            const uint32_t a0 = __float_as_uint(Qs[(w16 + g) * 68 + k0 + tig]);
            const uint32_t a1 = __float_as_uint(Qs[(w16 + g + 8) * 68 + k0 + tig]);
            const uint32_t a2 = __float_as_uint(Qs[(w16 + g) * 68 + k0 + tig + 4]);
            const uint32_t a3 = __float_as_uint(Qs[(w16 + g + 8) * 68 + k0 + tig + 4]);
#pragma unroll
            for (int n = 0; n < 8; n++) {
                const uint32_t b0 = __float_as_uint(Kb[(n * 8 + g) * 68 + k0 + tig]);
                const uint32_t b1 = __float_as_uint(Kb[(n * 8 + g) * 68 + k0 + tig + 4]);
                MMA_TF32(s[n], a0, a1, a2, a3, b0, b1);
            }
        }

        // online softmax (rows g and g+8, quad-reduced)
        float t0 = -1e30f, t1 = -1e30f;
#pragma unroll
        for (int n = 0; n < 8; n++) {
            t0 = fmaxf(t0, fmaxf(s[n][0], s[n][1]));
            t1 = fmaxf(t1, fmaxf(s[n][2], s[n][3]));
        }
        t0 = fmaxf(t0, __shfl_xor_sync(0xffffffffu, t0, 1));
        t0 = fmaxf(t0, __shfl_xor_sync(0xffffffffu, t0, 2));
        t1 = fmaxf(t1, __shfl_xor_sync(0xffffffffu, t1, 1));
        t1 = fmaxf(t1, __shfl_xor_sync(0xffffffffu, t1, 2));
        const float nm0 = fmaxf(m0r, t0), nm1 = fmaxf(m1r, t1);
        const float cr0 = __expf(m0r - nm0), cr1 = __expf(m1r - nm1);
        m0r = nm0; m1r = nm1;
        float ls0 = 0.f, ls1 = 0.f;
#pragma unroll
        for (int n = 0; n < 8; n++) {
            const float p0 = __expf(s[n][0] - nm0);
            const float p1 = __expf(s[n][1] - nm0);
            const float p2 = __expf(s[n][2] - nm1);
            const float p3 = __expf(s[n][3] - nm1);
            ls0 += p0 + p1; ls1 += p2 + p3;
            float2 pa; pa.x = to_tf32(p0); pa.y = to_tf32(p1);
            float2 pb; pb.x = to_tf32(p2); pb.y = to_tf32(p3);
            *(float2*)&Ps[(w16 + g) * 68 + n * 8 + tig * 2] = pa;
            *(float2*)&Ps[(w16 + g + 8) * 68 + n * 8 + tig * 2] = pb;
        }
        ls0 += __shfl_xor_sync(0xffffffffu, ls0, 1);
        ls0 += __shfl_xor_sync(0xffffffffu, ls0, 2);
        ls1 += __shfl_xor_sync(0xffffffffu, ls1, 1);
        ls1 += __shfl_xor_sync(0xffffffffu, ls1, 2);
        l0r = l0r * cr0 + ls0;
        l1r = l1r * cr1 + ls1;
#pragma unroll
        for (int n = 0; n < 8; n++) {
            oc[n][0] *= cr0; oc[n][1] *= cr0;
            oc[n][2] *= cr1; oc[n][3] *= cr1;
        }
        __syncwarp();

        // O += P V
#pragma unroll
        for (int ks = 0; ks < 8; ks++) {
            const int k0 = ks * 8;
            const uint32_t a0 = __float_as_uint(Ps[(w16 + g) * 68 + k0 + tig]);
            const uint32_t a1 = __float_as_uint(Ps[(w16 + g + 8) * 68 + k0 + tig]);
            const uint32_t a2 = __float_as_uint(Ps[(w16 + g) * 68 + k0 + tig + 4]);
            const uint32_t a3 = __float_as_uint(Ps[(w16 + g + 8) * 68 + k0 + tig + 4]);
#pragma unroll
            for (int n = 0; n < 8; n++) {
                const uint32_t b0 = __float_as_uint(Vb[(n * 8 + g) * 68 + k0 + tig]);
                const uint32_t b1 = __float_as_uint(Vb[(n * 8 + g) * 68 + k0 + tig + 4]);
                MMA_TF32(oc[n], a0, a1, a2, a3, b0, b1);
            }
        }

        if (tile < 15) {
            __syncthreads();
            float* Kn = Ks + (buf ^ 1) * 64 * 68;
            float* Vn = Vt + (buf ^ 1) * 64 * 68;
#pragma unroll
            for (int i = 0; i < 4; i++) {
                const int e = t + i * 256;
                const int rk = e >> 4, ck = e & 15;
                Kn[rk * 68 + ck * 4 + 0] = to_tf32(kvr[i].x);
                Kn[rk * 68 + ck * 4 + 1] = to_tf32(kvr[i].y);
                Kn[rk * 68 + ck * 4 + 2] = to_tf32(kvr[i].z);
                Kn[rk * 68 + ck * 4 + 3] = to_tf32(kvr[i].w);
                const int cv = (t >> 6) + i * 4;
                Vn[(cv * 4 + 0) * 68 + rkv] = to_tf32(vvr[i].x);
                Vn[(cv * 4 + 1) * 68 + rkv] = to_tf32(vvr[i].y);
                Vn[(cv * 4 + 2) * 68 + rkv] = to_tf32(vvr[i].z);
                Vn[(cv * 4 + 3) * 68 + rkv] = to_tf32(vvr[i].w);
            }
            __syncthreads();
        }
    }

    // epilogue: att output tf32 + d-permuted (feeds GEMM A).
    const float i0 = 1.f / l0r, i1 = 1.f / l1r;
    float* ob = out + (size_t)b * NPIX * CCH;
#pragma unroll
    for (int n = 0; n < 8; n++) {
        float* r0p = ob + (size_t)(q0 + w16 + g) * CCH + hq + n * 8;
        float* r1p = ob + (size_t)(q0 + w16 + g + 8) * CCH + hq + n * 8;
        r0p[P0]     = to_tf32(oc[n][0] * i0);
        r0p[P0 + 2] = to_tf32(oc[n][1] * i0);
        r1p[P0]     = to_tf32(oc[n][2] * i1);
        r1p[P0 + 2] = to_tf32(oc[n][3] * i1);
    }
}

// ---------------------------------------------------------------------------
// Depthwise 3x3 + exact GELU, token-major [8192][1024].
// Output tf32 + permuted (h2 feeds GEMM A).
// ---------------------------------------------------------------------------
__global__ __launch_bounds__(256)
void dwgelu_kernel(const float* __restrict__ x, const float* __restrict__ wd,
                   float* __restrict__ y)
{
    __shared__ float tile[10][34][32];
    const int c0 = blockIdx.x * 32;
    const int r0 = blockIdx.y * 8;
    const int b  = blockIdx.z;
    const int t  = threadIdx.x;
    const int ch = t & 31;

    for (int e = t; e < 10 * 34 * 32; e += 256) {
        const int cc  = e & 31;
        const int col = (e >> 5) % 34;
        const int r   = e / (34 * 32);
        const int hh = r0 + r - 1, ww = col - 1;
        float v = 0.f;
        if (hh >= 0 && hh < 32 && ww >= 0 && ww < 32)
            v = x[((size_t)b * NPIX + hh * 32 + ww) * HID + c0 + cc];
        tile[r][col][cc] = v;
    }
    float w9[9];
#pragma unroll
    for (int i = 0; i < 9; i++) w9[i] = wd[(size_t)(c0 + ch) * 9 + i];
    const int pc = permk(c0 + ch);
    __syncthreads();

    for (int e = t; e < 8 * 32 * 32; e += 256) {
        const int w = (e >> 5) & 31;
        const int r = e >> 10;
        float a = 0.f;
#pragma unroll
        for (int ky = 0; ky < 3; ky++)
#pragma unroll
            for (int kx = 0; kx < 3; kx++)
                a += w9[ky * 3 + kx] * tile[r + ky][w + kx][ch];
        y[((size_t)b * NPIX + (r0 + r) * 32 + w) * HID + pc] =
            to_tf32(0.5f * a * (1.f + erff(a * 0.70710678118654752f)));
    }
}

// ---------------------------------------------------------------------------
extern "C" void kernel_launch(void* const* d_in, const int* in_sizes, int n_in,
                              void* d_out, int out_size)
{
    const float* aop      = (const float*)d_in[0];
    const float* dop      = (const float*)d_in[1];
    const float* w_qconv  = (const float*)d_in[2];
    const float* w_kvconv = (const float*)d_in[3];
    const float* lnq1_w   = (const float*)d_in[4];
    const float* lnq1_b   = (const float*)d_in[5];
    const float* lnkv1_w  = (const float*)d_in[6];
    const float* lnkv1_b  = (const float*)d_in[7];
    const float* lnq2_w   = (const float*)d_in[8];
    const float* lnq2_b   = (const float*)d_in[9];
    const float* lnkv2_w  = (const float*)d_in[10];
    const float* lnkv2_b  = (const float*)d_in[11];
    const float* lnffn_w  = (const float*)d_in[12];
    const float* lnffn_b  = (const float*)d_in[13];
    const float* saq_qkv  = (const float*)d_in[14];
    const float* saq_proj = (const float*)d_in[15];
    const float* sakv_qkv = (const float*)d_in[16];
    const float* sakv_proj= (const float*)d_in[17];
    const float* ca_q     = (const float*)d_in[18];
    const float* ca_k     = (const float*)d_in[19];
    const float* ca_v     = (const float*)d_in[20];
    const float* ca_proj  = (const float*)d_in[21];
    const float* leff_in  = (const float*)d_in[22];
    const float* leff_dw  = (const float*)d_in[23];
    const float* leff_out = (const float*)d_in[24];
    float* out = (float*)d_out;

    float* S = nullptr;
    cudaGetSymbolAddress((void**)&S, g_scratch);
    float* ic   = S;
    float* qb   = ic   + IC_SZ;
    float* kvb  = qb   + C_SZ;
    float* lnb  = kvb  + C_SZ;
    float* qn   = lnb  + C_SZ;
    float* kvn  = qn   + C_SZ;
    float* att  = kvn  + C_SZ;
    float* xbuf = att  + C_SZ;
    float* qkv  = xbuf + C_SZ;
    float* h1   = qkv  + QKV_SZ;
    float* h2   = h1   + H_SZ;
    float* wp   = h2   + H_SZ;

    // permuted tf32 weight copies
    float* p_wq3   = wp;
    float* p_wk5   = p_wq3   + 589824;
    float* p_saqkv = p_wk5   + 1638400;
    float* p_saprj = p_saqkv + 196608;
    float* p_skqkv = p_saprj + 65536;
    float* p_skprj = p_skqkv + 196608;
    float* p_caq   = p_skprj + 65536;
    float* p_cak   = p_caq   + 65536;
    float* p_cav   = p_cak   + 65536;
    float* p_caprj = p_cav   + 65536;
    float* p_lin   = p_caprj + 65536;
    float* p_lout  = p_lin   + 262144;

    const int GEMM_SM = 2 * 5120 * 2 * 4;    // 81920
    const int ATTN_SM = (128 * 68 + 2 * 64 * 68 + 2 * 64 * 68 + 128 * 68) * 4; // 139264
    cudaFuncSetAttribute(gemm_tc,     cudaFuncAttributeMaxDynamicSharedMemorySize, GEMM_SM);
    cudaFuncSetAttribute(attn_kernel, cudaFuncAttributeMaxDynamicSharedMemorySize, ATTN_SM);

    // fused weight prep (one launch)
    PrepArgs pa;
    pa.src[0] = w_qconv;   pa.dst[0] = p_wq3;   pa.len[0] = 589824;
    pa.src[1] = w_kvconv;  pa.dst[1] = p_wk5;   pa.len[1] = 1638400;
    pa.src[2] = saq_qkv;   pa.dst[2] = p_saqkv; pa.len[2] = 196608;
    pa.src[3] = saq_proj;  pa.dst[3] = p_saprj; pa.len[3] = 65536;
    pa.src[4] = sakv_qkv;  pa.dst[4] = p_skqkv; pa.len[4] = 196608;
    pa.src[5] = sakv_proj; pa.dst[5] = p_skprj; pa.len[5] = 65536;
    pa.src[6] = ca_q;      pa.dst[6] = p_caq;   pa.len[6] = 65536;
    pa.src[7] = ca_k;      pa.dst[7] = p_cak;   pa.len[7] = 65536;
    pa.src[8] = ca_v;      pa.dst[8] = p_cav;   pa.len[8] = 65536;
    pa.src[9] = ca_proj;   pa.dst[9] = p_caprj; pa.len[9] = 65536;
    pa.src[10] = leff_in;  pa.dst[10] = p_lin;  pa.len[10] = 262144;
    pa.src[11] = leff_out; pa.dst[11] = p_lout; pa.len[11] = 262144;
    int prep_total = 589824 + 1638400 + 2 * 196608 + 6 * 65536 + 2 * 262144;
    prep_all<<<(prep_total + 255) / 256, 256>>>(pa);

    const dim3 g256(8, 2, B_), g768(8, 6, B_), g1024t(8, 8, B_);
    const dim3 gattn(8, 4, B_);
    const dim3 gi2c(4, 32, B_);
    const dim3 gdw(32, 4, B_);

    // ---- q branch ----
    im2col_kernel<3><<<gi2c, 256>>>(aop, ic);
    gemm_tc<<<g256, 256, GEMM_SM>>>(ic, 2304, p_wq3, nullptr, 0, qb, 256, 2304, 0);
    ln_kernel<<<1024, 256>>>(qb, lnq1_w, lnq1_b, lnb);
    gemm_tc<<<g768, 256, GEMM_SM>>>(lnb, 256, p_saqkv, nullptr, 0, qkv, 768, 256, 0);
    attn_kernel<<<gattn, 256, ATTN_SM>>>(qkv, att);
    gemm_tc<<<g256, 256, GEMM_SM>>>(att, 256, p_saprj, qb, 256, qb, 256, 256, 0);
    ln_kernel<<<1024, 256>>>(qb, lnq2_w, lnq2_b, qn);

    // ---- kv branch ----
    im2col_kernel<5><<<gi2c, 256>>>(dop, ic);
    gemm_tc<<<g256, 256, GEMM_SM>>>(ic, 6400, p_wk5, nullptr, 0, kvb, 256, 6400, 0);
    ln_kernel<<<1024, 256>>>(kvb, lnkv1_w, lnkv1_b, lnb);
    gemm_tc<<<g768, 256, GEMM_SM>>>(lnb, 256, p_skqkv, nullptr, 0, qkv, 768, 256, 0);
    attn_kernel<<<gattn, 256, ATTN_SM>>>(qkv, att);
    gemm_tc<<<g256, 256, GEMM_SM>>>(att, 256, p_skprj, kvb, 256, kvb, 256, 256, 0);
    ln_kernel<<<1024, 256>>>(kvb, lnkv2_w, lnkv2_b, kvn);

    // ---- cross attention ----
    gemm_tc<<<g256, 256, GEMM_SM>>>(qn,  256, p_caq,   nullptr, 0, qkv,       768, 256, 0);
    gemm_tc<<<g256, 256, GEMM_SM>>>(kvn, 256, p_cak,   nullptr, 0, qkv + 256, 768, 256, 0);
    gemm_tc<<<g256, 256, GEMM_SM>>>(kvn, 256, p_cav,   nullptr, 0, qkv + 512, 768, 256, 0);
    attn_kernel<<<gattn, 256, ATTN_SM>>>(qkv, att);
    gemm_tc<<<g256, 256, GEMM_SM>>>(att, 256, p_caprj, qb, 256, xbuf, 256, 256, 0);

    // ---- LeFF ----
    ln_kernel<<<1024, 256>>>(xbuf, lnffn_w, lnffn_b, lnb);
    gemm_tc<<<g1024t, 256, GEMM_SM>>>(lnb, 256, p_lin, nullptr, 0, h1, 1024, 256, 0);
    dwgelu_kernel<<<gdw, 256>>>(h1, leff_dw, h2);
    gemm_tc<<<g256, 256, GEMM_SM>>>(h2, 1024, p_lout, xbuf, 256, out, 256, 1024, 1);
}

// round 11
// speedup vs baseline: 1.1465x; 1.0339x over previous
#include <cuda_runtime.h>
#include <math.h>
#include <stdint.h>

#define B_    8
#define CCH   256
#define NPIX  1024
#define HID   1024
#define NTOK  (B_ * NPIX)   // 8192

// scratch layout (floats)
static const size_t IC_SZ  = (size_t)B_ * NPIX * 6400;   // 52.4M
static const size_t C_SZ   = (size_t)NTOK * CCH;         // 2M
static const size_t QKV_SZ = (size_t)NTOK * 768;         // 6M
static const size_t H_SZ   = (size_t)NTOK * HID;         // 8M
__device__ float g_scratch[92ull * 1024 * 1024];

extern __shared__ char dyn_smem[];

__device__ __forceinline__ float to_tf32(float x) {
    float r;
    asm("cvt.rna.tf32.f32 %0, %1;" : "=f"(r) : "f"(x));
    return r;
}
__device__ __forceinline__ uint32_t smem_addr(const void* p) {
    return (uint32_t)__cvta_generic_to_shared(p);
}
__device__ __forceinline__ void cp16(uint32_t dst, const void* src) {
    asm volatile("cp.async.ca.shared.global [%0], [%1], 16;" :: "r"(dst), "l"(src));
}
// k-permutation within each 8-block: newpos(k) = (k&3)*2 + ((k>>2)&1)
__device__ __forceinline__ int permk(int k) {
    return (k & ~7) | (((k & 3) << 1) | ((k >> 2) & 1));
}

#define MMA_TF32(acc, a0, a1, a2, a3, b0, b1) \
    asm volatile( \
        "mma.sync.aligned.m16n8k8.row.col.f32.tf32.tf32.f32 " \
        "{%0,%1,%2,%3}, {%4,%5,%6,%7}, {%8,%9}, {%0,%1,%2,%3};" \
        : "+f"((acc)[0]), "+f"((acc)[1]), "+f"((acc)[2]), "+f"((acc)[3]) \
        : "r"(a0), "r"(a1), "r"(a2), "r"(a3), "r"(b0), "r"(b1))

// ---------------------------------------------------------------------------
// fused weight prep: tf32-round + k-permute, all 12 weights in one launch.
// ca_k/ca_v are packed into one contiguous 512x256 weight.
// ---------------------------------------------------------------------------
struct PrepArgs {
    const float* src[12];
    float*       dst[12];
    int          len[12];
};
__global__ __launch_bounds__(256)
void prep_all(PrepArgs a)
{
    int i = blockIdx.x * 256 + threadIdx.x;
#pragma unroll
    for (int s = 0; s < 12; s++) {
        if (i < a.len[s]) {
            a.dst[s][permk(i)] = to_tf32(__ldg(a.src[s] + i));
            return;
        }
        i -= a.len[s];
    }
}

// ---------------------------------------------------------------------------
// tf32 mma.sync GEMM on PRE-PERMUTED tf32 inputs (A and Wt both [rows][K] with
// k-permuted columns). Y (+residual R) in NORMAL fp32 layout.
// Block 128x128x32, 8 warps, cp.async double buffer, smem [2][128][40].
// ---------------------------------------------------------------------------
__global__ __launch_bounds__(256, 2)
void gemm_tc(const float* __restrict__ A, size_t ldA,
             const float* __restrict__ Wt,
             const float* __restrict__ R, size_t ldR,
             float* __restrict__ Y, size_t ldY,
             int K, int transY)
{
    float* As = (float*)dyn_smem;        // [2][128*40]
    float* Bs = As + 2 * 5120;           // [2][128*40]

    const int t = threadIdx.x;
    const int wid = t >> 5, lane = t & 31;
    const int g = lane >> 2, tig = lane & 3;
    const int warp_m = (wid & 1) * 64;
    const int warp_n = (wid >> 1) * 32;
    const int r0l = t >> 3, q0l = t & 7;

    const float* Ab = A  + (size_t)blockIdx.z * NPIX * ldA + (size_t)blockIdx.x * 128 * ldA;
    const float* Bb = Wt + (size_t)blockIdx.y * 128 * (size_t)K;

    const uint32_t sA = smem_addr(As), sB = smem_addr(Bs);

    float acc[4][4][4];
#pragma unroll
    for (int im = 0; im < 4; im++)
#pragma unroll
        for (int in = 0; in < 4; in++)
#pragma unroll
            for (int c = 0; c < 4; c++) acc[im][in][c] = 0.f;

    const int nk = K >> 5;

#pragma unroll
    for (int i = 0; i < 4; i++) {
        const int r = r0l + i * 32;
        cp16(sA + (uint32_t)(r * 40 + q0l * 4) * 4, Ab + (size_t)r * ldA + q0l * 4);
        cp16(sB + (uint32_t)(r * 40 + q0l * 4) * 4, Bb + (size_t)r * K   + q0l * 4);
    }
    asm volatile("cp.async.commit_group;");

    for (int c = 0; c < nk; c++) {
        asm volatile("cp.async.wait_group 0;");
        __syncthreads();
        if (c + 1 < nk) {
            const int kk = (c + 1) << 5;
            const uint32_t boff = (uint32_t)((c + 1) & 1) * 5120;
#pragma unroll
            for (int i = 0; i < 4; i++) {
                const int r = r0l + i * 32;
                cp16(sA + (boff + r * 40 + q0l * 4) * 4, Ab + (size_t)r * ldA + kk + q0l * 4);
                cp16(sB + (boff + r * 40 + q0l * 4) * 4, Bb + (size_t)r * K   + kk + q0l * 4);
            }
            asm volatile("cp.async.commit_group;");
        }
        const float* Ac = As + (c & 1) * 5120;
        const float* Bc = Bs + (c & 1) * 5120;
#pragma unroll
        for (int ks = 0; ks < 4; ks++) {
            const int k0 = ks * 8;
            float2 au[4], al[4];
#pragma unroll
            for (int im = 0; im < 4; im++) {
                au[im] = *(const float2*)&Ac[(warp_m + im * 16 + g) * 40 + k0 + 2 * tig];
                al[im] = *(const float2*)&Ac[(warp_m + im * 16 + g + 8) * 40 + k0 + 2 * tig];
            }
#pragma unroll
            for (int in = 0; in < 4; in++) {
                const float2 bv = *(const float2*)&Bc[(warp_n + in * 8 + g) * 40 + k0 + 2 * tig];
#pragma unroll
                for (int im = 0; im < 4; im++) {
                    MMA_TF32(acc[im][in],
                             __float_as_uint(au[im].x), __float_as_uint(al[im].x),
                             __float_as_uint(au[im].y), __float_as_uint(al[im].y),
                             __float_as_uint(bv.x), __float_as_uint(bv.y));
                }
            }
        }
    }

    const int b = blockIdx.z;
    if (!transY) {
        float* Yb = Y + (size_t)b * NPIX * ldY;
        const float* Rb = R ? R + (size_t)b * NPIX * ldR : (const float*)0;
#pragma unroll
        for (int im = 0; im < 4; im++) {
#pragma unroll
            for (int half = 0; half < 2; half++) {
                const int tok = blockIdx.x * 128 + warp_m + im * 16 + g + half * 8;
#pragma unroll
                for (int in = 0; in < 4; in++) {
                    const int col = blockIdx.y * 128 + warp_n + in * 8 + tig * 2;
                    float2 v;
                    v.x = acc[im][in][half * 2 + 0];
                    v.y = acc[im][in][half * 2 + 1];
                    if (Rb) {
                        float2 rr = *(const float2*)(Rb + (size_t)tok * ldR + col);
                        v.x += rr.x; v.y += rr.y;
                    }
                    *(float2*)(Yb + (size_t)tok * ldY + col) = v;
                }
            }
        }
    } else {
        float* Yb = Y + (size_t)b * ldY * NPIX;
        const float* Rb = R ? R + (size_t)b * NPIX * ldR : (const float*)0;
#pragma unroll
        for (int im = 0; im < 4; im++) {
#pragma unroll
            for (int half = 0; half < 2; half++) {
                const int tok = blockIdx.x * 128 + warp_m + im * 16 + g + half * 8;
#pragma unroll
                for (int in = 0; in < 4; in++) {
                    const int col = blockIdx.y * 128 + warp_n + in * 8 + tig * 2;
                    float v0 = acc[im][in][half * 2 + 0];
                    float v1 = acc[im][in][half * 2 + 1];
                    if (Rb) {
                        float2 rr = *(const float2*)(Rb + (size_t)tok * ldR + col);
                        v0 += rr.x; v1 += rr.y;
                    }
                    Yb[(size_t)(col + 0) * NPIX + tok] = v0;
                    Yb[(size_t)(col + 1) * NPIX + tok] = v1;
                }
            }
        }
    }
}

// ---------------------------------------------------------------------------
// im2col: NCHW -> [B][1024 tok][C*KS*KS], tf32-rounded, k-permuted.
// ---------------------------------------------------------------------------
template <int KS>
__global__ __launch_bounds__(256)
void im2col_kernel(const float* __restrict__ in, float* __restrict__ out)
{
    constexpr int PAD  = KS / 2;
    constexpr int TAPS = KS * KS;
    constexpr int KTOT = CCH * TAPS;
    __shared__ float smv[64 * KS * 36];
    const int c0 = blockIdx.x * 64;
    const int h  = blockIdx.y;
    const int b  = blockIdx.z;
    const int t  = threadIdx.x;

    for (int e = t; e < 64 * KS * 36; e += 256) {
        const int cc = e % 36;
        const int r  = (e / 36) % KS;
        const int c  = e / (36 * KS);
        const int hh = h + r - PAD;
        const int ww = cc - PAD;
        float v = 0.f;
        if (hh >= 0 && hh < 32 && ww >= 0 && ww < 32)
            v = in[((size_t)b * CCH + c0 + c) * NPIX + hh * 32 + ww];
        smv[(c * KS + r) * 36 + cc] = v;
    }
    __syncthreads();
    for (int e = t; e < 32 * 64 * TAPS; e += 256) {
        const int w   = e / (64 * TAPS);
        const int rem = e % (64 * TAPS);
        const int c   = rem / TAPS;
        const int tap = rem % TAPS;
        const int ky  = tap / KS, kx = tap % KS;
        const int k   = (c0 + c) * TAPS + tap;
        out[((size_t)b * NPIX + h * 32 + w) * KTOT + permk(k)] =
            to_tf32(smv[(c * KS + ky) * 36 + (w + kx)]);
    }
}

// ---------------------------------------------------------------------------
// LayerNorm over channels, token-major [8192][256]. Warp per token.
// Output: tf32-rounded, k-permuted (GEMM A operand).
// ---------------------------------------------------------------------------
__global__ __launch_bounds__(256)
void ln_kernel(const float* __restrict__ x, const float* __restrict__ w,
               const float* __restrict__ bs, float* __restrict__ y)
{
    const int warp = threadIdx.x >> 5, lane = threadIdx.x & 31;
    const size_t tok = (size_t)blockIdx.x * 8 + warp;
    const float* xr = x + tok * CCH;
    float4 v0 = *(const float4*)(xr + lane * 4);
    float4 v1 = *(const float4*)(xr + 128 + lane * 4);
    float s  = v0.x + v0.y + v0.z + v0.w + v1.x + v1.y + v1.z + v1.w;
    float s2 = v0.x*v0.x + v0.y*v0.y + v0.z*v0.z + v0.w*v0.w
             + v1.x*v1.x + v1.y*v1.y + v1.z*v1.z + v1.w*v1.w;
#pragma unroll
    for (int o = 16; o > 0; o >>= 1) {
        s  += __shfl_xor_sync(0xffffffffu, s,  o);
        s2 += __shfl_xor_sync(0xffffffffu, s2, o);
    }
    const float mu = s * (1.f / 256.f);
    const float is = rsqrtf(s2 * (1.f / 256.f) - mu * mu + 1e-5f);
    float4 w0 = *(const float4*)(w + lane * 4);
    float4 w1 = *(const float4*)(w + 128 + lane * 4);
    float4 b0 = *(const float4*)(bs + lane * 4);
    float4 b1 = *(const float4*)(bs + 128 + lane * 4);
    float* yr = y + tok * CCH;
    float r0[4], r1[4];
    r0[0] = (v0.x - mu) * is * w0.x + b0.x; r0[1] = (v0.y - mu) * is * w0.y + b0.y;
    r0[2] = (v0.z - mu) * is * w0.z + b0.z; r0[3] = (v0.w - mu) * is * w0.w + b0.w;
    r1[0] = (v1.x - mu) * is * w1.x + b1.x; r1[1] = (v1.y - mu) * is * w1.y + b1.y;
    r1[2] = (v1.z - mu) * is * w1.z + b1.z; r1[3] = (v1.w - mu) * is * w1.w + b1.w;
#pragma unroll
    for (int j = 0; j < 4; j++) {
        yr[permk(lane * 4 + j)]       = to_tf32(r0[j]);
        yr[permk(128 + lane * 4 + j)] = to_tf32(r1[j]);
    }
}

// ---------------------------------------------------------------------------
// Flash attention, tf32 mma. Single K/V buffer, 2 CTAs/SM (one wave of 256
// blocks on 296 dual slots); latency hidden by the co-resident CTA.
// qkv [B][1024][768] token-major; out [B][1024][256] tf32 k-permuted.
// Block 128 queries / 8 warps; softmax 1/8 scale folded into Q staging.
// ---------------------------------------------------------------------------
__global__ __launch_bounds__(256, 2)
void attn_kernel(const float* __restrict__ qkv, float* __restrict__ out)
{
    float* sm = (float*)dyn_smem;
    float* Qs = sm;                      // [128][68]
    float* Ks = Qs + 128 * 68;           // [64][68]
    float* Vt = Ks + 64 * 68;            // [64][68]  (d, key)
    float* Ps = Vt + 64 * 68;            // [128][68]

    const int b = blockIdx.z, h = blockIdx.y;
    const int q0 = blockIdx.x * 128;
    const int hq = h * 64;
    const float* base = qkv + (size_t)b * NPIX * 768;

    const int t = threadIdx.x;
    const int wid = t >> 5, lane = t & 31;
    const int g = lane >> 2, tig = lane & 3;
    const int w16 = wid * 16;

    // Q staged once (scaled by 1/8, tf32)
#pragma unroll
    for (int i = 0; i < 8; i++) {
        const int e = t + i * 256;
        const int r = e >> 4, c = e & 15;
        float4 v = *(const float4*)(base + (size_t)(q0 + r) * 768 + hq + c * 4);
        Qs[r * 68 + c * 4 + 0] = to_tf32(v.x * 0.125f);
        Qs[r * 68 + c * 4 + 1] = to_tf32(v.y * 0.125f);
        Qs[r * 68 + c * 4 + 2] = to_tf32(v.z * 0.125f);
        Qs[r * 68 + c * 4 + 3] = to_tf32(v.w * 0.125f);
    }

    float oc[8][4];
#pragma unroll
    for (int n = 0; n < 8; n++)
#pragma unroll
        for (int c = 0; c < 4; c++) oc[n][c] = 0.f;
    float m0r = -1e30f, m1r = -1e30f, l0r = 0.f, l1r = 0.f;

    const int rkv = t & 63;
    const int P0 = ((tig & 1) << 2) | (tig >> 1);   // perm(2*tig); perm(2*tig+1)=P0+2

    for (int tile = 0; tile < 16; tile++) {
        const size_t m0 = (size_t)tile * 64;
        if (tile > 0) __syncthreads();   // prior PV consumers done
        // stage K/V tile (single buffer)
#pragma unroll
        for (int i = 0; i < 4; i++) {
            const int e = t + i * 256;
            const int rk = e >> 4, ck = e & 15;
            float4 kv = *(const float4*)(base + (m0 + rk) * 768 + 256 + hq + ck * 4);
            Ks[rk * 68 + ck * 4 + 0] = to_tf32(kv.x);
            Ks[rk * 68 + ck * 4 + 1] = to_tf32(kv.y);
            Ks[rk * 68 + ck * 4 + 2] = to_tf32(kv.z);
            Ks[rk * 68 + ck * 4 + 3] = to_tf32(kv.w);
            const int cv = (t >> 6) + i * 4;
            float4 vv = *(const float4*)(base + (m0 + rkv) * 768 + 512 + hq + cv * 4);
            Vt[(cv * 4 + 0) * 68 + rkv] = to_tf32(vv.x);
            Vt[(cv * 4 + 1) * 68 + rkv] = to_tf32(vv.y);
            Vt[(cv * 4 + 2) * 68 + rkv] = to_tf32(vv.z);
            Vt[(cv * 4 + 3) * 68 + rkv] = to_tf32(vv.w);
        }
        __syncthreads();

        // S = (Q/8) K^T
        float s[8][4];
#pragma unroll
        for (int n = 0; n < 8; n++)
#pragma unroll
            for (int c = 0; c < 4; c++) s[n][c] = 0.f;
#pragma unroll
        for (int ks = 0; ks < 8; ks++) {
            const int k0 = ks * 8;
            const uint32_t a0 = __float_as_uint(Qs[(w16 + g) * 68 + k0 + tig]);
            const uint32_t a1 = __float_as_uint(Qs[(w16 + g + 8) * 68 + k0 + tig]);
            const uint32_t a2 = __float_as_uint(Qs[(w16 + g) * 68 + k0 + tig + 4]);
            const uint32_t a3 = __float_as_uint(Qs[(w16 + g + 8) * 68 + k0 + tig + 4]);
#pragma unroll
            for (int n = 0; n < 8; n++) {
                const uint32_t b0 = __float_as_uint(Ks[(n * 8 + g) * 68 + k0 + tig]);
                const uint32_t b1 = __float_as_uint(Ks[(n * 8 + g) * 68 + k0 + tig + 4]);
                MMA_TF32(s[n], a0, a1, a2, a3, b0, b1);
            }
        }

        // online softmax (rows g and g+8, quad-reduced)
        float t0 = -1e30f, t1 = -1e30f;
#pragma unroll
        for (int n = 0; n < 8; n++) {
            t0 = fmaxf(t0, fmaxf(s[n][0], s[n][1]));
            t1 = fmaxf(t1, fmaxf(s[n][2], s[n][3]));
        }
        t0 = fmaxf(t0, __shfl_xor_sync(0xffffffffu, t0, 1));
        t0 = fmaxf(t0, __shfl_xor_sync(0xffffffffu, t0, 2));
        t1 = fmaxf(t1, __shfl_xor_sync(0xffffffffu, t1, 1));
        t1 = fmaxf(t1, __shfl_xor_sync(0xffffffffu, t1, 2));
        const float nm0 = fmaxf(m0r, t0), nm1 = fmaxf(m1r, t1);
        const float cr0 = __expf(m0r - nm0), cr1 = __expf(m1r - nm1);
        m0r = nm0; m1r = nm1;
        float ls0 = 0.f, ls1 = 0.f;
#pragma unroll
        for (int n = 0; n < 8; n++) {
            const float p0 = __expf(s[n][0] - nm0);
            const float p1 = __expf(s[n][1] - nm0);
            const float p2 = __expf(s[n][2] - nm1);
            const float p3 = __expf(s[n][3] - nm1);
            ls0 += p0 + p1; ls1 += p2 + p3;
            float2 pa; pa.x = to_tf32(p0); pa.y = to_tf32(p1);
            float2 pb; pb.x = to_tf32(p2); pb.y = to_tf32(p3);
            *(float2*)&Ps[(w16 + g) * 68 + n * 8 + tig * 2] = pa;
            *(float2*)&Ps[(w16 + g + 8) * 68 + n * 8 + tig * 2] = pb;
        }
        ls0 += __shfl_xor_sync(0xffffffffu, ls0, 1);
        ls0 += __shfl_xor_sync(0xffffffffu, ls0, 2);
        ls1 += __shfl_xor_sync(0xffffffffu, ls1, 1);
        ls1 += __shfl_xor_sync(0xffffffffu, ls1, 2);
        l0r = l0r * cr0 + ls0;
        l1r = l1r * cr1 + ls1;
#pragma unroll
        for (int n = 0; n < 8; n++) {
            oc[n][0] *= cr0; oc[n][1] *= cr0;
            oc[n][2] *= cr1; oc[n][3] *= cr1;
        }
        __syncwarp();

        // O += P V
#pragma unroll
        for (int ks = 0; ks < 8; ks++) {
            const int k0 = ks * 8;
            const uint32_t a0 = __float_as_uint(Ps[(w16 + g) * 68 + k0 + tig]);
            const uint32_t a1 = __float_as_uint(Ps[(w16 + g + 8) * 68 + k0 + tig]);
            const uint32_t a2 = __float_as_uint(Ps[(w16 + g) * 68 + k0 + tig + 4]);
            const uint32_t a3 = __float_as_uint(Ps[(w16 + g + 8) * 68 + k0 + tig + 4]);
#pragma unroll
            for (int n = 0; n < 8; n++) {
                const uint32_t b0 = __float_as_uint(Vt[(n * 8 + g) * 68 + k0 + tig]);
                const uint32_t b1 = __float_as_uint(Vt[(n * 8 + g) * 68 + k0 + tig + 4]);
                MMA_TF32(oc[n], a0, a1, a2, a3, b0, b1);
            }
        }
    }

    // epilogue: att output tf32 + d-permuted (feeds GEMM A).
    const float i0 = 1.f / l0r, i1 = 1.f / l1r;
    float* ob = out + (size_t)b * NPIX * CCH;
#pragma unroll
    for (int n = 0; n < 8; n++) {
        float* r0p = ob + (size_t)(q0 + w16 + g) * CCH + hq + n * 8;
        float* r1p = ob + (size_t)(q0 + w16 + g + 8) * CCH + hq + n * 8;
        r0p[P0]     = to_tf32(oc[n][0] * i0);
        r0p[P0 + 2] = to_tf32(oc[n][1] * i0);
        r1p[P0]     = to_tf32(oc[n][2] * i1);
        r1p[P0 + 2] = to_tf32(oc[n][3] * i1);
    }
}

// ---------------------------------------------------------------------------
// Depthwise 3x3 + exact GELU, token-major [8192][1024].
// Output tf32 + permuted (h2 feeds GEMM A).
// ---------------------------------------------------------------------------
__global__ __launch_bounds__(256)
void dwgelu_kernel(const float* __restrict__ x, const float* __restrict__ wd,
                   float* __restrict__ y)
{
    __shared__ float tile[10][34][32];
    const int c0 = blockIdx.x * 32;
    const int r0 = blockIdx.y * 8;
    const int b  = blockIdx.z;
    const int t  = threadIdx.x;
    const int ch = t & 31;

    for (int e = t; e < 10 * 34 * 32; e += 256) {
        const int cc  = e & 31;
        const int col = (e >> 5) % 34;
        const int r   = e / (34 * 32);
        const int hh = r0 + r - 1, ww = col - 1;
        float v = 0.f;
        if (hh >= 0 && hh < 32 && ww >= 0 && ww < 32)
            v = x[((size_t)b * NPIX + hh * 32 + ww) * HID + c0 + cc];
        tile[r][col][cc] = v;
    }
    float w9[9];
#pragma unroll
    for (int i = 0; i < 9; i++) w9[i] = wd[(size_t)(c0 + ch) * 9 + i];
    const int pc = permk(c0 + ch);
    __syncthreads();

    for (int e = t; e < 8 * 32 * 32; e += 256) {
        const int w = (e >> 5) & 31;
        const int r = e >> 10;
        float a = 0.f;
#pragma unroll
        for (int ky = 0; ky < 3; ky++)
#pragma unroll
            for (int kx = 0; kx < 3; kx++)
                a += w9[ky * 3 + kx] * tile[r + ky][w + kx][ch];
        y[((size_t)b * NPIX + (r0 + r) * 32 + w) * HID + pc] =
            to_tf32(0.5f * a * (1.f + erff(a * 0.70710678118654752f)));
    }
}

// ---------------------------------------------------------------------------
extern "C" void kernel_launch(void* const* d_in, const int* in_sizes, int n_in,
                              void* d_out, int out_size)
{
    const float* aop      = (const float*)d_in[0];
    const float* dop      = (const float*)d_in[1];
    const float* w_qconv  = (const float*)d_in[2];
    const float* w_kvconv = (const float*)d_in[3];
    const float* lnq1_w   = (const float*)d_in[4];
    const float* lnq1_b   = (const float*)d_in[5];
    const float* lnkv1_w  = (const float*)d_in[6];
    const float* lnkv1_b  = (const float*)d_in[7];
    const float* lnq2_w   = (const float*)d_in[8];
    const float* lnq2_b   = (const float*)d_in[9];
    const float* lnkv2_w  = (const float*)d_in[10];
    const float* lnkv2_b  = (const float*)d_in[11];
    const float* lnffn_w  = (const float*)d_in[12];
    const float* lnffn_b  = (const float*)d_in[13];
    const float* saq_qkv  = (const float*)d_in[14];
    const float* saq_proj = (const float*)d_in[15];
    const float* sakv_qkv = (const float*)d_in[16];
    const float* sakv_proj= (const float*)d_in[17];
    const float* ca_q     = (const float*)d_in[18];
    const float* ca_k     = (const float*)d_in[19];
    const float* ca_v     = (const float*)d_in[20];
    const float* ca_proj  = (const float*)d_in[21];
    const float* leff_in  = (const float*)d_in[22];
    const float* leff_dw  = (const float*)d_in[23];
    const float* leff_out = (const float*)d_in[24];
    float* out = (float*)d_out;

    float* S = nullptr;
    cudaGetSymbolAddress((void**)&S, g_scratch);
    float* ic   = S;
    float* qb   = ic   + IC_SZ;
    float* kvb  = qb   + C_SZ;
    float* lnb  = kvb  + C_SZ;
    float* qn   = lnb  + C_SZ;
    float* kvn  = qn   + C_SZ;
    float* att  = kvn  + C_SZ;
    float* xbuf = att  + C_SZ;
    float* qkv  = xbuf + C_SZ;
    float* h1   = qkv  + QKV_SZ;
    float* h2   = h1   + H_SZ;
    float* wp   = h2   + H_SZ;

    // permuted tf32 weight copies
    float* p_wq3   = wp;
    float* p_wk5   = p_wq3   + 589824;
    float* p_saqkv = p_wk5   + 1638400;
    float* p_saprj = p_saqkv + 196608;
    float* p_skqkv = p_saprj + 65536;
    float* p_skprj = p_skqkv + 196608;
    float* p_caq   = p_skprj + 65536;
    float* p_cakv  = p_caq   + 65536;     // packed [ca_k; ca_v] 512x256
    float* p_caprj = p_cakv  + 131072;
    float* p_lin   = p_caprj + 65536;
    float* p_lout  = p_lin   + 262144;

    const int GEMM_SM = 2 * 5120 * 2 * 4;    // 81920
    const int ATTN_SM = (128 * 68 + 64 * 68 + 64 * 68 + 128 * 68) * 4; // 104448
    cudaFuncSetAttribute(gemm_tc,     cudaFuncAttributeMaxDynamicSharedMemorySize, GEMM_SM);
    cudaFuncSetAttribute(attn_kernel, cudaFuncAttributeMaxDynamicSharedMemorySize, ATTN_SM);

    // fused weight prep (one launch); ca_k/ca_v packed contiguously
    PrepArgs pa;
    pa.src[0] = w_qconv;   pa.dst[0] = p_wq3;           pa.len[0] = 589824;
    pa.src[1] = w_kvconv;  pa.dst[1] = p_wk5;           pa.len[1] = 1638400;
    pa.src[2] = saq_qkv;   pa.dst[2] = p_saqkv;         pa.len[2] = 196608;
    pa.src[3] = saq_proj;  pa.dst[3] = p_saprj;         pa.len[3] = 65536;
    pa.src[4] = sakv_qkv;  pa.dst[4] = p_skqkv;         pa.len[4] = 196608;
    pa.src[5] = sakv_proj; pa.dst[5] = p_skprj;         pa.len[5] = 65536;
    pa.src[6] = ca_q;      pa.dst[6] = p_caq;           pa.len[6] = 65536;
    pa.src[7] = ca_k;      pa.dst[7] = p_cakv;          pa.len[7] = 65536;
    pa.src[8] = ca_v;      pa.dst[8] = p_cakv + 65536;  pa.len[8] = 65536;
    pa.src[9] = ca_proj;   pa.dst[9] = p_caprj;         pa.len[9] = 65536;
    pa.src[10] = leff_in;  pa.dst[10] = p_lin;          pa.len[10] = 262144;
    pa.src[11] = leff_out; pa.dst[11] = p_lout;         pa.len[11] = 262144;
    int prep_total = 589824 + 1638400 + 2 * 196608 + 6 * 65536 + 2 * 262144;
    prep_all<<<(prep_total + 255) / 256, 256>>>(pa);

    const dim3 g256(8, 2, B_), g512(8, 4, B_), g768(8, 6, B_), g1024t(8, 8, B_);
    const dim3 gattn(8, 4, B_);
    const dim3 gi2c(4, 32, B_);
    const dim3 gdw(32, 4, B_);

    // ---- q branch ----
    im2col_kernel<3><<<gi2c, 256>>>(aop, ic);
    gemm_tc<<<g256, 256, GEMM_SM>>>(ic, 2304, p_wq3, nullptr, 0, qb, 256, 2304, 0);
    ln_kernel<<<1024, 256>>>(qb, lnq1_w, lnq1_b, lnb);
    gemm_tc<<<g768, 256, GEMM_SM>>>(lnb, 256, p_saqkv, nullptr, 0, qkv, 768, 256, 0);
    attn_kernel<<<gattn, 256, ATTN_SM>>>(qkv, att);
    gemm_tc<<<g256, 256, GEMM_SM>>>(att, 256, p_saprj, qb, 256, qb, 256, 256, 0);
    ln_kernel<<<1024, 256>>>(qb, lnq2_w, lnq2_b, qn);

    // ---- kv branch ----
    im2col_kernel<5><<<gi2c, 256>>>(dop, ic);
    gemm_tc<<<g256, 256, GEMM_SM>>>(ic, 6400, p_wk5, nullptr, 0, kvb, 256, 6400, 0);
    ln_kernel<<<1024, 256>>>(kvb, lnkv1_w, lnkv1_b, lnb);
    gemm_tc<<<g768, 256, GEMM_SM>>>(lnb, 256, p_skqkv, nullptr, 0, qkv, 768, 256, 0);
    attn_kernel<<<gattn, 256, ATTN_SM>>>(qkv, att);
    gemm_tc<<<g256, 256, GEMM_SM>>>(att, 256, p_skprj, kvb, 256, kvb, 256, 256, 0);
    ln_kernel<<<1024, 256>>>(kvb, lnkv2_w, lnkv2_b, kvn);

    // ---- cross attention ----
    gemm_tc<<<g256, 256, GEMM_SM>>>(qn,  256, p_caq,  nullptr, 0, qkv,       768, 256, 0);
    gemm_tc<<<g512, 256, GEMM_SM>>>(kvn, 256, p_cakv, nullptr, 0, qkv + 256, 768, 256, 0);
    attn_kernel<<<gattn, 256, ATTN_SM>>>(qkv, att);
    gemm_tc<<<g256, 256, GEMM_SM>>>(att, 256, p_caprj, qb, 256, xbuf, 256, 256, 0);

    // ---- LeFF ----
    ln_kernel<<<1024, 256>>>(xbuf, lnffn_w, lnffn_b, lnb);
    gemm_tc<<<g1024t, 256, GEMM_SM>>>(lnb, 256, p_lin, nullptr, 0, h1, 1024, 256, 0);
    dwgelu_kernel<<<gdw, 256>>>(h1, leff_dw, h2);
    gemm_tc<<<g256, 256, GEMM_SM>>>(h2, 1024, p_lout, xbuf, 256, out, 256, 1024, 1);
}

// round 13
// speedup vs baseline: 1.1810x; 1.0301x over previous
#include <cuda_runtime.h>
#include <math.h>
#include <stdint.h>

#define B_    8
#define CCH   256
#define NPIX  1024
#define HID   1024
#define NTOK  (B_ * NPIX)   // 8192

// scratch layout (floats)
static const size_t IC_SZ  = (size_t)B_ * NPIX * 6400;   // 52.4M
static const size_t C_SZ   = (size_t)NTOK * CCH;         // 2M
static const size_t QK_SZ  = (size_t)NTOK * 512;         // 4M
__device__ float g_scratch[92ull * 1024 * 1024];

extern __shared__ char dyn_smem[];

__device__ __forceinline__ float to_tf32(float x) {
    float r;
    asm("cvt.rna.tf32.f32 %0, %1;" : "=f"(r) : "f"(x));
    return r;
}
__device__ __forceinline__ uint32_t smem_addr(const void* p) {
    return (uint32_t)__cvta_generic_to_shared(p);
}
__device__ __forceinline__ void cp16(uint32_t dst, const void* src) {
    asm volatile("cp.async.ca.shared.global [%0], [%1], 16;" :: "r"(dst), "l"(src));
}
// k-permutation within each 8-block: newpos(k) = (k&3)*2 + ((k>>2)&1)
__device__ __forceinline__ int permk(int k) {
    return (k & ~7) | (((k & 3) << 1) | ((k >> 2) & 1));
}

#define MMA_TF32(acc, a0, a1, a2, a3, b0, b1) \
    asm volatile( \
        "mma.sync.aligned.m16n8k8.row.col.f32.tf32.tf32.f32 " \
        "{%0,%1,%2,%3}, {%4,%5,%6,%7}, {%8,%9}, {%0,%1,%2,%3};" \
        : "+f"((acc)[0]), "+f"((acc)[1]), "+f"((acc)[2]), "+f"((acc)[3]) \
        : "r"(a0), "r"(a1), "r"(a2), "r"(a3), "r"(b0), "r"(b1))

// ---------------------------------------------------------------------------
// fused weight prep: tf32-round + k-permute + optional scale, one launch.
// Q-projection weights pre-scaled by 0.125 (exact power-of-2).
// ---------------------------------------------------------------------------
struct PrepArgs {
    const float* src[14];
    float*       dst[14];
    int          len[14];
    float        scl[14];
};
__global__ __launch_bounds__(256)
void prep_all(PrepArgs a)
{
    int i = blockIdx.x * 256 + threadIdx.x;
#pragma unroll
    for (int s = 0; s < 14; s++) {
        if (i < a.len[s]) {
            a.dst[s][permk(i)] = to_tf32(__ldg(a.src[s] + i) * a.scl[s]);
            return;
        }
        i -= a.len[s];
    }
}

// ---------------------------------------------------------------------------
// tf32 mma.sync GEMM on PRE-PERMUTED tf32 inputs (A and Wt both [rows][K] with
// k-permuted columns). Y (+residual R) fp32; rnd=1 -> tf32-rounded outputs.
// Block 128x128x32, 8 warps, cp.async double buffer, smem [2][128][40].
// ---------------------------------------------------------------------------
__global__ __launch_bounds__(256, 2)
void gemm_tc(const float* __restrict__ A, size_t ldA,
             const float* __restrict__ Wt,
             const float* __restrict__ R, size_t ldR,
             float* __restrict__ Y, size_t ldY,
             int K, int transY, int rnd)
{
    float* As = (float*)dyn_smem;        // [2][128*40]
    float* Bs = As + 2 * 5120;           // [2][128*40]

    const int t = threadIdx.x;
    const int wid = t >> 5, lane = t & 31;
    const int g = lane >> 2, tig = lane & 3;
    const int warp_m = (wid & 1) * 64;
    const int warp_n = (wid >> 1) * 32;
    const int r0l = t >> 3, q0l = t & 7;

    const float* Ab = A  + (size_t)blockIdx.z * NPIX * ldA + (size_t)blockIdx.x * 128 * ldA;
    const float* Bb = Wt + (size_t)blockIdx.y * 128 * (size_t)K;

    const uint32_t sA = smem_addr(As), sB = smem_addr(Bs);

    float acc[4][4][4];
#pragma unroll
    for (int im = 0; im < 4; im++)
#pragma unroll
        for (int in = 0; in < 4; in++)
#pragma unroll
            for (int c = 0; c < 4; c++) acc[im][in][c] = 0.f;

    const int nk = K >> 5;

#pragma unroll
    for (int i = 0; i < 4; i++) {
        const int r = r0l + i * 32;
        cp16(sA + (uint32_t)(r * 40 + q0l * 4) * 4, Ab + (size_t)r * ldA + q0l * 4);
        cp16(sB + (uint32_t)(r * 40 + q0l * 4) * 4, Bb + (size_t)r * K   + q0l * 4);
    }
    asm volatile("cp.async.commit_group;");

    for (int c = 0; c < nk; c++) {
        asm volatile("cp.async.wait_group 0;");
        __syncthreads();
        if (c + 1 < nk) {
            const int kk = (c + 1) << 5;
            const uint32_t boff = (uint32_t)((c + 1) & 1) * 5120;
#pragma unroll
            for (int i = 0; i < 4; i++) {
                const int r = r0l + i * 32;
                cp16(sA + (boff + r * 40 + q0l * 4) * 4, Ab + (size_t)r * ldA + kk + q0l * 4);
                cp16(sB + (boff + r * 40 + q0l * 4) * 4, Bb + (size_t)r * K   + kk + q0l * 4);
            }
            asm volatile("cp.async.commit_group;");
        }
        const float* Ac = As + (c & 1) * 5120;
        const float* Bc = Bs + (c & 1) * 5120;
#pragma unroll
        for (int ks = 0; ks < 4; ks++) {
            const int k0 = ks * 8;
            float2 au[4], al[4];
#pragma unroll
            for (int im = 0; im < 4; im++) {
                au[im] = *(const float2*)&Ac[(warp_m + im * 16 + g) * 40 + k0 + 2 * tig];
                al[im] = *(const float2*)&Ac[(warp_m + im * 16 + g + 8) * 40 + k0 + 2 * tig];
            }
#pragma unroll
            for (int in = 0; in < 4; in++) {
                const float2 bv = *(const float2*)&Bc[(warp_n + in * 8 + g) * 40 + k0 + 2 * tig];
#pragma unroll
                for (int im = 0; im < 4; im++) {
                    MMA_TF32(acc[im][in],
                             __float_as_uint(au[im].x), __float_as_uint(al[im].x),
                             __float_as_uint(au[im].y), __float_as_uint(al[im].y),
                             __float_as_uint(bv.x), __float_as_uint(bv.y));
                }
            }
        }
    }

    const int b = blockIdx.z;
    if (!transY) {
        float* Yb = Y + (size_t)b * NPIX * ldY;
        const float* Rb = R ? R + (size_t)b * NPIX * ldR : (const float*)0;
#pragma unroll
        for (int im = 0; im < 4; im++) {
#pragma unroll
            for (int half = 0; half < 2; half++) {
                const int tok = blockIdx.x * 128 + warp_m + im * 16 + g + half * 8;
#pragma unroll
                for (int in = 0; in < 4; in++) {
                    const int col = blockIdx.y * 128 + warp_n + in * 8 + tig * 2;
                    float2 v;
                    v.x = acc[im][in][half * 2 + 0];
                    v.y = acc[im][in][half * 2 + 1];
                    if (Rb) {
                        float2 rr = *(const float2*)(Rb + (size_t)tok * ldR + col);
                        v.x += rr.x; v.y += rr.y;
                    }
                    if (rnd) { v.x = to_tf32(v.x); v.y = to_tf32(v.y); }
                    *(float2*)(Yb + (size_t)tok * ldY + col) = v;
                }
            }
        }
    } else {
        float* Yb = Y + (size_t)b * ldY * NPIX;
        const float* Rb = R ? R + (size_t)b * NPIX * ldR : (const float*)0;
#pragma unroll
        for (int im = 0; im < 4; im++) {
#pragma unroll
            for (int half = 0; half < 2; half++) {
                const int tok = blockIdx.x * 128 + warp_m + im * 16 + g + half * 8;
#pragma unroll
                for (int in = 0; in < 4; in++) {
                    const int col = blockIdx.y * 128 + warp_n + in * 8 + tig * 2;
                    float v0 = acc[im][in][half * 2 + 0];
                    float v1 = acc[im][in][half * 2 + 1];
                    if (Rb) {
                        float2 rr = *(const float2*)(Rb + (size_t)tok * ldR + col);
                        v0 += rr.x; v1 += rr.y;
                    }
                    if (rnd) { v0 = to_tf32(v0); v1 = to_tf32(v1); }
                    Yb[(size_t)(col + 0) * NPIX + tok] = v0;
                    Yb[(size_t)(col + 1) * NPIX + tok] = v1;
                }
            }
        }
    }
}

// ---------------------------------------------------------------------------
// im2col: NCHW -> [B][1024 tok][C*KS*KS], tf32-rounded, k-permuted.
// ---------------------------------------------------------------------------
template <int KS>
__global__ __launch_bounds__(256)
void im2col_kernel(const float* __restrict__ in, float* __restrict__ out)
{
    constexpr int PAD  = KS / 2;
    constexpr int TAPS = KS * KS;
    constexpr int KTOT = CCH * TAPS;
    __shared__ float smv[64 * KS * 36];
    const int c0 = blockIdx.x * 64;
    const int h  = blockIdx.y;
    const int b  = blockIdx.z;
    const int t  = threadIdx.x;

    for (int e = t; e < 64 * KS * 36; e += 256) {
        const int cc = e % 36;
        const int r  = (e / 36) % KS;
        const int c  = e / (36 * KS);
        const int hh = h + r - PAD;
        const int ww = cc - PAD;
        float v = 0.f;
        if (hh >= 0 && hh < 32 && ww >= 0 && ww < 32)
            v = in[((size_t)b * CCH + c0 + c) * NPIX + hh * 32 + ww];
        smv[(c * KS + r) * 36 + cc] = v;
    }
    __syncthreads();
    for (int e = t; e < 32 * 64 * TAPS; e += 256) {
        const int w   = e / (64 * TAPS);
        const int rem = e % (64 * TAPS);
        const int c   = rem / TAPS;
        const int tap = rem % TAPS;
        const int ky  = tap / KS, kx = tap % KS;
        const int k   = (c0 + c) * TAPS + tap;
        out[((size_t)b * NPIX + h * 32 + w) * KTOT + permk(k)] =
            to_tf32(smv[(c * KS + ky) * 36 + (w + kx)]);
    }
}

// ---------------------------------------------------------------------------
// LayerNorm over channels, token-major [8192][256]. Warp per token.
// Output: tf32-rounded, k-permuted (GEMM A operand).
// ---------------------------------------------------------------------------
__global__ __launch_bounds__(256)
void ln_kernel(const float* __restrict__ x, const float* __restrict__ w,
               const float* __restrict__ bs, float* __restrict__ y)
{
    const int warp = threadIdx.x >> 5, lane = threadIdx.x & 31;
    const size_t tok = (size_t)blockIdx.x * 8 + warp;
    const float* xr = x + tok * CCH;
    float4 v0 = *(const float4*)(xr + lane * 4);
    float4 v1 = *(const float4*)(xr + 128 + lane * 4);
    float s  = v0.x + v0.y + v0.z + v0.w + v1.x + v1.y + v1.z + v1.w;
    float s2 = v0.x*v0.x + v0.y*v0.y + v0.z*v0.z + v0.w*v0.w
             + v1.x*v1.x + v1.y*v1.y + v1.z*v1.z + v1.w*v1.w;
#pragma unroll
    for (int o = 16; o > 0; o >>= 1) {
        s  += __shfl_xor_sync(0xffffffffu, s,  o);
        s2 += __shfl_xor_sync(0xffffffffu, s2, o);
    }
    const float mu = s * (1.f / 256.f);
    const float is = rsqrtf(s2 * (1.f / 256.f) - mu * mu + 1e-5f);
    float4 w0 = *(const float4*)(w + lane * 4);
    float4 w1 = *(const float4*)(w + 128 + lane * 4);
    float4 b0 = *(const float4*)(bs + lane * 4);
    float4 b1 = *(const float4*)(bs + 128 + lane * 4);
    float* yr = y + tok * CCH;
    float r0[4], r1[4];
    r0[0] = (v0.x - mu) * is * w0.x + b0.x; r0[1] = (v0.y - mu) * is * w0.y + b0.y;
    r0[2] = (v0.z - mu) * is * w0.z + b0.z; r0[3] = (v0.w - mu) * is * w0.w + b0.w;
    r1[0] = (v1.x - mu) * is * w1.x + b1.x; r1[1] = (v1.y - mu) * is * w1.y + b1.y;
    r1[2] = (v1.z - mu) * is * w1.z + b1.z; r1[3] = (v1.w - mu) * is * w1.w + b1.w;
#pragma unroll
    for (int j = 0; j < 4; j++) {
        yr[permk(lane * 4 + j)]       = to_tf32(r0[j]);
        yr[permk(128 + lane * 4 + j)] = to_tf32(r1[j]);
    }
}

// ---------------------------------------------------------------------------
// Flash attention, tf32 mma. Inputs are PRE-ROUNDED tf32:
//   qk [B][1024][512] token-major (Q cols 0-255 pre-scaled by 1/8, K 256-511)
//   vT [B][256][1024] channel-major (V transposed)
// All staging is raw cp.async (no cvt, no transpose). 2 CTAs/SM, one wave.
// out [B][1024][256] tf32 k-permuted. Block 128 queries / 8 warps.
// ---------------------------------------------------------------------------
__global__ __launch_bounds__(256, 2)
void attn_kernel(const float* __restrict__ qk, const float* __restrict__ vT,
                 float* __restrict__ out)
{
    float* sm = (float*)dyn_smem;
    float* Qs = sm;                      // [128][68]
    float* Ks = Qs + 128 * 68;           // [64][68]
    float* Vt = Ks + 64 * 68;            // [64][68]  (d, key)
    float* Ps = Vt + 64 * 68;            // [128][68]

    const int b = blockIdx.z, h = blockIdx.y;
    const int q0 = blockIdx.x * 128;
    const int hq = h * 64;
    const float* qkb = qk + (size_t)b * NPIX * 512;
    const float* vtb = vT + ((size_t)b * 256 + hq) * NPIX;

    const int t = threadIdx.x;
    const int wid = t >> 5, lane = t & 31;
    const int g = lane >> 2, tig = lane & 3;
    const int w16 = wid * 16;

    const uint32_t sQ = smem_addr(Qs), sK = smem_addr(Ks), sV = smem_addr(Vt);

    // stage Q (once) + tile 0 K/V — all cp.async
#pragma unroll
    for (int i = 0; i < 8; i++) {
        const int e = t + i * 256;
        const int r = e >> 4, c = e & 15;
        cp16(sQ + (uint32_t)(r * 68 + c * 4) * 4,
             qkb + (size_t)(q0 + r) * 512 + hq + c * 4);
    }
#pragma unroll
    for (int i = 0; i < 4; i++) {
        const int e = t + i * 256;
        const int rk = e >> 4, ck = e & 15;
        cp16(sK + (uint32_t)(rk * 68 + ck * 4) * 4, qkb + (size_t)rk * 512 + 256 + hq + ck * 4);
        cp16(sV + (uint32_t)(rk * 68 + ck * 4) * 4, vtb + (size_t)rk * NPIX + ck * 4);
    }
    asm volatile("cp.async.commit_group;");

    float oc[8][4];
#pragma unroll
    for (int n = 0; n < 8; n++)
#pragma unroll
        for (int c = 0; c < 4; c++) oc[n][c] = 0.f;
    float m0r = -1e30f, m1r = -1e30f, l0r = 0.f, l1r = 0.f;

    const int P0 = ((tig & 1) << 2) | (tig >> 1);   // perm(2*tig); perm(2*tig+1)=P0+2

    for (int tile = 0; tile < 16; tile++) {
        asm volatile("cp.async.wait_group 0;");
        __syncthreads();

        // S = (Q/8) K^T
        float s[8][4];
#pragma unroll
        for (int n = 0; n < 8; n++)
#pragma unroll
            for (int c = 0; c < 4; c++) s[n][c] = 0.f;
#pragma unroll
        for (int ks = 0; ks < 8; ks++) {
            const int k0 = ks * 8;
            const uint32_t a0 = __float_as_uint(Qs[(w16 + g) * 68 + k0 + tig]);
            const uint32_t a1 = __float_as_uint(Qs[(w16 + g + 8) * 68 + k0 + tig]);
            const uint32_t a2 = __float_as_uint(Qs[(w16 + g) * 68 + k0 + tig + 4]);
            const uint32_t a3 = __float_as_uint(Qs[(w16 + g + 8) * 68 + k0 + tig + 4]);
#pragma unroll
            for (int n = 0; n < 8; n++) {
                const uint32_t b0 = __float_as_uint(Ks[(n * 8 + g) * 68 + k0 + tig]);
                const uint32_t b1 = __float_as_uint(Ks[(n * 8 + g) * 68 + k0 + tig + 4]);
                MMA_TF32(s[n], a0, a1, a2, a3, b0, b1);
            }
        }

        // online softmax (rows g and g+8, quad-reduced)
        float t0 = -1e30f, t1 = -1e30f;
#pragma unroll
        for (int n = 0; n < 8; n++) {
            t0 = fmaxf(t0, fmaxf(s[n][0], s[n][1]));
            t1 = fmaxf(t1, fmaxf(s[n][2], s[n][3]));
        }
        t0 = fmaxf(t0, __shfl_xor_sync(0xffffffffu, t0, 1));
        t0 = fmaxf(t0, __shfl_xor_sync(0xffffffffu, t0, 2));
        t1 = fmaxf(t1, __shfl_xor_sync(0xffffffffu, t1, 1));
        t1 = fmaxf(t1, __shfl_xor_sync(0xffffffffu, t1, 2));
        const float nm0 = fmaxf(m0r, t0), nm1 = fmaxf(m1r, t1);
        const float cr0 = __expf(m0r - nm0), cr1 = __expf(m1r - nm1);
        m0r = nm0; m1r = nm1;
        float ls0 = 0.f, ls1 = 0.f;
#pragma unroll
        for (int n = 0; n < 8; n++) {
            const float p0 = __expf(s[n][0] - nm0);
            const float p1 = __expf(s[n][1] - nm0);
            const float p2 = __expf(s[n][2] - nm1);
            const float p3 = __expf(s[n][3] - nm1);
            ls0 += p0 + p1; ls1 += p2 + p3;
            float2 pa; pa.x = to_tf32(p0); pa.y = to_tf32(p1);
            float2 pb; pb.x = to_tf32(p2); pb.y = to_tf32(p3);
            *(float2*)&Ps[(w16 + g) * 68 + n * 8 + tig * 2] = pa;
            *(float2*)&Ps[(w16 + g + 8) * 68 + n * 8 + tig * 2] = pb;
        }
        ls0 += __shfl_xor_sync(0xffffffffu, ls0, 1);
        ls0 += __shfl_xor_sync(0xffffffffu, ls0, 2);
        ls1 += __shfl_xor_sync(0xffffffffu, ls1, 1);
        ls1 += __shfl_xor_sync(0xffffffffu, ls1, 2);
        l0r = l0r * cr0 + ls0;
        l1r = l1r * cr1 + ls1;
#pragma unroll
        for (int n = 0; n < 8; n++) {
            oc[n][0] *= cr0; oc[n][1] *= cr0;
            oc[n][2] *= cr1; oc[n][3] *= cr1;
        }
        __syncwarp();

        // O += P V
#pragma unroll
        for (int ks = 0; ks < 8; ks++) {
            const int k0 = ks * 8;
            const uint32_t a0 = __float_as_uint(Ps[(w16 + g) * 68 + k0 + tig]);
            const uint32_t a1 = __float_as_uint(Ps[(w16 + g + 8) * 68 + k0 + tig]);
            const uint32_t a2 = __float_as_uint(Ps[(w16 + g) * 68 + k0 + tig + 4]);
            const uint32_t a3 = __float_as_uint(Ps[(w16 + g + 8) * 68 + k0 + tig + 4]);
#pragma unroll
            for (int n = 0; n < 8; n++) {
                const uint32_t b0 = __float_as_uint(Vt[(n * 8 + g) * 68 + k0 + tig]);
                const uint32_t b1 = __float_as_uint(Vt[(n * 8 + g) * 68 + k0 + tig + 4]);
                MMA_TF32(oc[n], a0, a1, a2, a3, b0, b1);
            }
        }

        if (tile < 15) {
            __syncthreads();   // all warps done reading Ks/Vt
            const size_t m0 = (size_t)(tile + 1) * 64;
#pragma unroll
            for (int i = 0; i < 4; i++) {
                const int e = t + i * 256;
                const int rk = e >> 4, ck = e & 15;
                cp16(sK + (uint32_t)(rk * 68 + ck * 4) * 4,
                     qkb + (m0 + rk) * 512 + 256 + hq + ck * 4);
                cp16(sV + (uint32_t)(rk * 68 + ck * 4) * 4,
                     vtb + (size_t)rk * NPIX + m0 + ck * 4);
            }
            asm volatile("cp.async.commit_group;");
        }
    }

    // epilogue: att output tf32 + d-permuted (feeds GEMM A).
    const float i0 = 1.f / l0r, i1 = 1.f / l1r;
    float* ob = out + (size_t)b * NPIX * CCH;
#pragma unroll
    for (int n = 0; n < 8; n++) {
        float* r0p = ob + (size_t)(q0 + w16 + g) * CCH + hq + n * 8;
        float* r1p = ob + (size_t)(q0 + w16 + g + 8) * CCH + hq + n * 8;
        r0p[P0]     = to_tf32(oc[n][0] * i0);
        r0p[P0 + 2] = to_tf32(oc[n][1] * i0);
        r1p[P0]     = to_tf32(oc[n][2] * i1);
        r1p[P0 + 2] = to_tf32(oc[n][3] * i1);
    }
}

// ---------------------------------------------------------------------------
// Depthwise 3x3 + exact GELU, token-major [8192][1024].
// Output tf32 + permuted (h2 feeds GEMM A).
// ---------------------------------------------------------------------------
__global__ __launch_bounds__(256)
void dwgelu_kernel(const float* __restrict__ x, const float* __restrict__ wd,
                   float* __restrict__ y)
{
    __shared__ float tile[10][34][32];
    const int c0 = blockIdx.x * 32;
    const int r0 = blockIdx.y * 8;
    const int b  = blockIdx.z;
    const int t  = threadIdx.x;
    const int ch = t & 31;

    for (int e = t; e < 10 * 34 * 32; e += 256) {
        const int cc  = e & 31;
        const int col = (e >> 5) % 34;
        const int r   = e / (34 * 32);
        const int hh = r0 + r - 1, ww = col - 1;
        float v = 0.f;
        if (hh >= 0 && hh < 32 && ww >= 0 && ww < 32)
            v = x[((size_t)b * NPIX + hh * 32 + ww) * HID + c0 + cc];
        tile[r][col][cc] = v;
    }
    float w9[9];
#pragma unroll
    for (int i = 0; i < 9; i++) w9[i] = wd[(size_t)(c0 + ch) * 9 + i];
    const int pc = permk(c0 + ch);
    __syncthreads();

    for (int e = t; e < 8 * 32 * 32; e += 256) {
        const int w = (e >> 5) & 31;
        const int r = e >> 10;
        float a = 0.f;
#pragma unroll
        for (int ky = 0; ky < 3; ky++)
#pragma unroll
            for (int kx = 0; kx < 3; kx++)
                a += w9[ky * 3 + kx] * tile[r + ky][w + kx][ch];
        y[((size_t)b * NPIX + (r0 + r) * 32 + w) * HID + pc] =
            to_tf32(0.5f * a * (1.f + erff(a * 0.70710678118654752f)));
    }
}

// ---------------------------------------------------------------------------
extern "C" void kernel_launch(void* const* d_in, const int* in_sizes, int n_in,
                              void* d_out, int out_size)
{
    const float* aop      = (const float*)d_in[0];
    const float* dop      = (const float*)d_in[1];
    const float* w_qconv  = (const float*)d_in[2];
    const float* w_kvconv = (const float*)d_in[3];
    const float* lnq1_w   = (const float*)d_in[4];
    const float* lnq1_b   = (const float*)d_in[5];
    const float* lnkv1_w  = (const float*)d_in[6];
    const float* lnkv1_b  = (const float*)d_in[7];
    const float* lnq2_w   = (const float*)d_in[8];
    const float* lnq2_b   = (const float*)d_in[9];
    const float* lnkv2_w  = (const float*)d_in[10];
    const float* lnkv2_b  = (const float*)d_in[11];
    const float* lnffn_w  = (const float*)d_in[12];
    const float* lnffn_b  = (const float*)d_in[13];
    const float* saq_qkv  = (const float*)d_in[14];
    const float* saq_proj = (const float*)d_in[15];
    const float* sakv_qkv = (const float*)d_in[16];
    const float* sakv_proj= (const float*)d_in[17];
    const float* ca_q     = (const float*)d_in[18];
    const float* ca_k     = (const float*)d_in[19];
    const float* ca_v     = (const float*)d_in[20];
    const float* ca_proj  = (const float*)d_in[21];
    const float* leff_in  = (const float*)d_in[22];
    const float* leff_dw  = (const float*)d_in[23];
    const float* leff_out = (const float*)d_in[24];
    float* out = (float*)d_out;

    float* S = nullptr;
    cudaGetSymbolAddress((void**)&S, g_scratch);
    float* ic   = S;
    float* qb   = ic   + IC_SZ;
    float* kvb  = qb   + C_SZ;
    float* lnb  = kvb  + C_SZ;
    float* qn   = lnb  + C_SZ;
    float* kvn  = qn   + C_SZ;
    float* att  = kvn  + C_SZ;
    float* xbuf = att  + C_SZ;
    float* qkB  = xbuf + C_SZ;          // [B][1024][512]
    float* vTB  = qkB  + QK_SZ;         // [B][256][1024]
    float* h1   = vTB  + C_SZ;
    float* h2   = h1   + (size_t)NTOK * HID;
    float* wp   = h2   + (size_t)NTOK * HID;

    // permuted tf32 weight copies
    float* p_wq3   = wp;
    float* p_wk5   = p_wq3   + 589824;
    float* p_saqkv = p_wk5   + 1638400;   // 768x256 (Q rows pre-scaled)
    float* p_saprj = p_saqkv + 196608;
    float* p_skqkv = p_saprj + 65536;     // 768x256
    float* p_skprj = p_skqkv + 196608;
    float* p_caq   = p_skprj + 65536;     // pre-scaled
    float* p_cak   = p_caq   + 65536;
    float* p_cav   = p_cak   + 65536;
    float* p_caprj = p_cav   + 65536;
    float* p_lin   = p_caprj + 65536;
    float* p_lout  = p_lin   + 262144;

    const int GEMM_SM = 2 * 5120 * 2 * 4;    // 81920
    const int ATTN_SM = (128 * 68 + 64 * 68 + 64 * 68 + 128 * 68) * 4; // 104448
    cudaFuncSetAttribute(gemm_tc,     cudaFuncAttributeMaxDynamicSharedMemorySize, GEMM_SM);
    cudaFuncSetAttribute(attn_kernel, cudaFuncAttributeMaxDynamicSharedMemorySize, ATTN_SM);

    // fused weight prep (one launch). Q-projection rows scaled by 0.125.
    PrepArgs pa;
    int s = 0;
    auto seg = [&](const float* src, float* dst, int len, float scl) {
        pa.src[s] = src; pa.dst[s] = dst; pa.len[s] = len; pa.scl[s] = scl; s++;
    };
    seg(w_qconv,          p_wq3,            589824,  1.f);
    seg(w_kvconv,         p_wk5,            1638400, 1.f);
    seg(saq_qkv,          p_saqkv,          65536,   0.125f);  // Q rows
    seg(saq_qkv + 65536,  p_saqkv + 65536,  131072,  1.f);     // K,V rows
    seg(saq_proj,         p_saprj,          65536,   1.f);
    seg(sakv_qkv,         p_skqkv,          65536,   0.125f);
    seg(sakv_qkv + 65536, p_skqkv + 65536,  131072,  1.f);
    seg(sakv_proj,        p_skprj,          65536,   1.f);
    seg(ca_q,             p_caq,            65536,   0.125f);
    seg(ca_k,             p_cak,            65536,   1.f);
    seg(ca_v,             p_cav,            65536,   1.f);
    seg(ca_proj,          p_caprj,          65536,   1.f);
    seg(leff_in,          p_lin,            262144,  1.f);
    seg(leff_out,         p_lout,           262144,  1.f);
    int prep_total = 589824 + 1638400 + 2 * 196608 + 6 * 65536 + 2 * 262144;
    prep_all<<<(prep_total + 255) / 256, 256>>>(pa);

    const dim3 g256(8, 2, B_), g512(8, 4, B_), g1024t(8, 8, B_);
    const dim3 gattn(8, 4, B_);
    const dim3 gi2c(4, 32, B_);
    const dim3 gdw(32, 4, B_);

    // ---- q branch ----
    im2col_kernel<3><<<gi2c, 256>>>(aop, ic);
    gemm_tc<<<g256, 256, GEMM_SM>>>(ic, 2304, p_wq3, nullptr, 0, qb, 256, 2304, 0, 0);
    ln_kernel<<<1024, 256>>>(qb, lnq1_w, lnq1_b, lnb);
    gemm_tc<<<g512, 256, GEMM_SM>>>(lnb, 256, p_saqkv, nullptr, 0, qkB, 512, 256, 0, 1);
    gemm_tc<<<g256, 256, GEMM_SM>>>(lnb, 256, p_saqkv + 512 * 256, nullptr, 0, vTB, 256, 256, 1, 1);
    attn_kernel<<<gattn, 256, ATTN_SM>>>(qkB, vTB, att);
    gemm_tc<<<g256, 256, GEMM_SM>>>(att, 256, p_saprj, qb, 256, qb, 256, 256, 0, 0);
    ln_kernel<<<1024, 256>>>(qb, lnq2_w, lnq2_b, qn);

    // ---- kv branch ----
    im2col_kernel<5><<<gi2c, 256>>>(dop, ic);
    gemm_tc<<<g256, 256, GEMM_SM>>>(ic, 6400, p_wk5, nullptr, 0, kvb, 256, 6400, 0, 0);
    ln_kernel<<<1024, 256>>>(kvb, lnkv1_w, lnkv1_b, lnb);
    gemm_tc<<<g512, 256, GEMM_SM>>>(lnb, 256, p_skqkv, nullptr, 0, qkB, 512, 256, 0, 1);
    gemm_tc<<<g256, 256, GEMM_SM>>>(lnb, 256, p_skqkv + 512 * 256, nullptr, 0, vTB, 256, 256, 1, 1);
    attn_kernel<<<gattn, 256, ATTN_SM>>>(qkB, vTB, att);
    gemm_tc<<<g256, 256, GEMM_SM>>>(att, 256, p_skprj, kvb, 256, kvb, 256, 256, 0, 0);
    ln_kernel<<<1024, 256>>>(kvb, lnkv2_w, lnkv2_b, kvn);

    // ---- cross attention ----
    gemm_tc<<<g256, 256, GEMM_SM>>>(qn,  256, p_caq, nullptr, 0, qkB,       512, 256, 0, 1);
    gemm_tc<<<g256, 256, GEMM_SM>>>(kvn, 256, p_cak, nullptr, 0, qkB + 256, 512, 256, 0, 1);
    gemm_tc<<<g256, 256, GEMM_SM>>>(kvn, 256, p_cav, nullptr, 0, vTB,       256, 256, 1, 1);
    attn_kernel<<<gattn, 256, ATTN_SM>>>(qkB, vTB, att);
    gemm_tc<<<g256, 256, GEMM_SM>>>(att, 256, p_caprj, qb, 256, xbuf, 256, 256, 0, 0);

    // ---- LeFF ----
    ln_kernel<<<1024, 256>>>(xbuf, lnffn_w, lnffn_b, lnb);
    gemm_tc<<<g1024t, 256, GEMM_SM>>>(lnb, 256, p_lin, nullptr, 0, h1, 1024, 256, 0, 0);
    dwgelu_kernel<<<gdw, 256>>>(h1, leff_dw, h2);
    gemm_tc<<<g256, 256, GEMM_SM>>>(h2, 1024, p_lout, xbuf, 256, out, 256, 1024, 1, 0);
}